// round 1
// baseline (speedup 1.0000x reference)
#include <cuda_runtime.h>

// ---------------- problem constants ----------------
#define BATCH 4
#define NQ    16384          // 4 * 64 * 64 latent vectors
#define EDIM  256
#define KCB   8192

// ---------------- scratch (static device memory; no allocation) ----------------
__device__ float g_h1[4 * 128 * 128 * 128];
__device__ float g_h2[4 * 128 * 64 * 64];
__device__ float g_h3[4 * 128 * 64 * 64];
__device__ float g_z[NQ * EDIM];          // [n][e]
__device__ float g_quant[NQ * EDIM];      // [n][e]
__device__ float g_q[4 * 128 * 64 * 64];
__device__ float g_d1[4 * 128 * 64 * 64];
__device__ float g_d2[4 * 128 * 128 * 128];
__device__ float g_znorm[NQ];
__device__ float g_cnorm[KCB];
__device__ float g_bestv[2 * NQ];
__device__ int   g_besti[2 * NQ];
__device__ int   g_idx[NQ];
__device__ float g_commit;

// =====================================================================
// Generic implicit-GEMM conv kernel.
//   MODE 0: normal conv (stride S, pad P, kernel KK)   weights [Cout][Cin][KK][KK]
//   MODE 2: ConvTranspose2d k=4,s=2,p=1 (direct, valid taps only)
//           weights torch layout [Cin][Cout][4][4]
//   INL  0: input NCHW        1: input [n][Cin] (1x1 conv from row-major vecs)
//   OUTL 0: output NCHW       1: output [n][Cout]
// Tile: 128 oc x 64 px, 256 threads, micro-tile 8 oc x 4 px.
// =====================================================================
template<int MODE, int KK, int S, int P, bool RELU, int INL, int OUTL>
__global__ __launch_bounds__(256)
void conv_gemm(const float* __restrict__ in, const float* __restrict__ w,
               const float* __restrict__ bias, float* __restrict__ out,
               int Cin, int Cout, int Hin, int Win, int Hout, int Wout,
               int woutShift)
{
    const int R = (MODE == 2) ? Cin * 4 : Cin * KK * KK;
    const int b = blockIdx.z;
    const int oc0 = blockIdx.y * 128;

    int pxbase = 0, oh_fixed = 0, par = 0;
    if (MODE == 2) { oh_fixed = blockIdx.x >> 1; par = blockIdx.x & 1; }
    else           { pxbase = blockIdx.x * 64; }

    __shared__ float ws[16][128];
    __shared__ float xs[16][68];

    const int tid = threadIdx.x;
    const int tx = tid & 15;   // px group (4 px each)
    const int ty = tid >> 4;   // oc group (8 oc each)

    float acc[8][4];
#pragma unroll
    for (int j = 0; j < 8; j++)
#pragma unroll
        for (int i = 0; i < 4; i++) acc[j][i] = 0.f;

    for (int r0 = 0; r0 < R; r0 += 16) {
        __syncthreads();
        // ---- stage weights: ws[r][oc] ----
        {
            int row = tid >> 1;        // oc within tile (0..127)
            int half = tid & 1;        // which 8-r half
            int oc = oc0 + row;
#pragma unroll
            for (int i = 0; i < 8; i++) {
                int r = r0 + half * 8 + i;
                float v = 0.f;
                if (r < R) {
                    if (MODE == 2) {
                        int ic = r >> 2, t = r & 3, th = t >> 1, tw = t & 1;
                        int kh = ((oh_fixed + 1) & 1) + 2 * th;
                        int kw = (1 - par) + 2 * tw;
                        v = w[((ic * Cout + oc) * 4 + kh) * 4 + kw];
                    } else {
                        v = w[oc * R + r];
                    }
                }
                ws[half * 8 + i][row] = v;
            }
        }
        // ---- stage inputs: xs[r][p] ----
#pragma unroll
        for (int i2 = 0; i2 < 4; i2++) {
            int li = tid + i2 * 256;
            int r, p;
            if (INL == 1) { r = li & 15; p = li >> 4; }
            else          { r = li >> 6; p = li & 63; }
            int rr = r0 + r;
            float v = 0.f;
            if (rr < R) {
                if (MODE == 2) {
                    int ic = rr >> 2, t = rr & 3, th = t >> 1, tw = t & 1;
                    int ow = par + 2 * p;
                    int ih = ((oh_fixed + 1) >> 1) - th;
                    int iw = ((ow + 1) >> 1) - tw;
                    if ((unsigned)ih < (unsigned)Hin && (unsigned)iw < (unsigned)Win)
                        v = in[((b * Cin + ic) * Hin + ih) * Win + iw];
                } else if (INL == 1) {
                    int n = b * (Hout * Wout) + pxbase + p;
                    v = in[n * Cin + rr];
                } else {
                    int ic = rr / (KK * KK);
                    int kr = rr - ic * KK * KK;
                    int kh = kr / KK, kw = kr - kh * KK;
                    int px = pxbase + p;
                    int oh = px >> woutShift;
                    int ow = px & (Wout - 1);
                    int ih = oh * S + kh - P;
                    int iw = ow * S + kw - P;
                    if ((unsigned)ih < (unsigned)Hin && (unsigned)iw < (unsigned)Win)
                        v = in[((b * Cin + ic) * Hin + ih) * Win + iw];
                }
            }
            xs[r][p] = v;
        }
        __syncthreads();
        // ---- compute ----
#pragma unroll
        for (int k = 0; k < 16; k++) {
            float4 xv = *reinterpret_cast<const float4*>(&xs[k][tx * 4]);
            float4 w0 = *reinterpret_cast<const float4*>(&ws[k][ty * 8]);
            float4 w1 = *reinterpret_cast<const float4*>(&ws[k][ty * 8 + 4]);
            float wv[8] = {w0.x, w0.y, w0.z, w0.w, w1.x, w1.y, w1.z, w1.w};
            float xf[4] = {xv.x, xv.y, xv.z, xv.w};
#pragma unroll
            for (int j = 0; j < 8; j++)
#pragma unroll
                for (int i = 0; i < 4; i++)
                    acc[j][i] = fmaf(wv[j], xf[i], acc[j][i]);
        }
    }

    // ---- epilogue ----
#pragma unroll
    for (int j = 0; j < 8; j++) {
        int oc = oc0 + ty * 8 + j;
        float bv = bias[oc];
#pragma unroll
        for (int i = 0; i < 4; i++) {
            float v = acc[j][i] + bv;
            if (RELU) v = fmaxf(v, 0.f);
            if (MODE == 2) {
                int ow = par + 2 * (tx * 4 + i);
                out[((b * Cout + oc) * Hout + oh_fixed) * Wout + ow] = v;
            } else if (OUTL == 1) {
                int n = b * (Hout * Wout) + pxbase + tx * 4 + i;
                out[n * Cout + oc] = v;
            } else {
                out[(b * Cout + oc) * (Hout * Wout) + pxbase + tx * 4 + i] = v;
            }
        }
    }
}

// =====================================================================
// row squared-norm over 256-wide rows (z and codebook)
// =====================================================================
__global__ void rownorm_kernel(const float* __restrict__ v, float* __restrict__ outn, int rows)
{
    int warp = threadIdx.x >> 5, lane = threadIdx.x & 31;
    int n = blockIdx.x * 8 + warp;
    if (n >= rows) return;
    const float* p = v + (size_t)n * 256;
    float s = 0.f;
#pragma unroll
    for (int k = 0; k < 8; k++) { float x = p[lane + 32 * k]; s = fmaf(x, x, s); }
#pragma unroll
    for (int off = 16; off; off >>= 1) s += __shfl_down_sync(0xffffffffu, s, off);
    if (lane == 0) outn[n] = s;
}

__global__ void zero_commit_kernel(float* c) { *c = 0.f; }

// =====================================================================
// VQ argmin: block = 64 z rows x 4096 codes (half, via blockIdx.y)
// score = fl(znorm + cnorm) - 2*dot, single rounding (matches reference)
// =====================================================================
__global__ __launch_bounds__(256)
void vq_argmin(const float* __restrict__ z, const float* __restrict__ cb,
               const float* __restrict__ znorm, const float* __restrict__ cnorm,
               float* __restrict__ bestv_out, int* __restrict__ besti_out)
{
    __shared__ float cs[16][128];
    __shared__ float zs[16][68];
    __shared__ float s_val[16][64];
    __shared__ int   s_idx[16][64];

    const int tid = threadIdx.x;
    const int tx = tid & 15, ty = tid >> 4;
    const int zbase = blockIdx.x * 64;

    float zn[4];
#pragma unroll
    for (int i = 0; i < 4; i++) zn[i] = znorm[zbase + tx * 4 + i];

    float bv[4] = {3.4e38f, 3.4e38f, 3.4e38f, 3.4e38f};
    int   bi[4] = {0, 0, 0, 0};

    for (int ct = 0; ct < 32; ct++) {
        const int cbase = (blockIdx.y * 32 + ct) * 128;
        float dot[8][4];
#pragma unroll
        for (int j = 0; j < 8; j++)
#pragma unroll
            for (int i = 0; i < 4; i++) dot[j][i] = 0.f;

        for (int r0 = 0; r0 < 256; r0 += 16) {
            __syncthreads();
            {
                int row = tid >> 1, half = tid & 1;
                const float* src = cb + (size_t)(cbase + row) * 256 + r0 + half * 8;
#pragma unroll
                for (int i = 0; i < 8; i++) cs[half * 8 + i][row] = src[i];
            }
#pragma unroll
            for (int i2 = 0; i2 < 4; i2++) {
                int li = tid + i2 * 256;
                int r = li & 15, p = li >> 4;
                zs[r][p] = z[(size_t)(zbase + p) * 256 + r0 + r];
            }
            __syncthreads();
#pragma unroll
            for (int k = 0; k < 16; k++) {
                float4 xv = *reinterpret_cast<const float4*>(&zs[k][tx * 4]);
                float4 w0 = *reinterpret_cast<const float4*>(&cs[k][ty * 8]);
                float4 w1 = *reinterpret_cast<const float4*>(&cs[k][ty * 8 + 4]);
                float wv[8] = {w0.x, w0.y, w0.z, w0.w, w1.x, w1.y, w1.z, w1.w};
                float xf[4] = {xv.x, xv.y, xv.z, xv.w};
#pragma unroll
                for (int j = 0; j < 8; j++)
#pragma unroll
                    for (int i = 0; i < 4; i++)
                        dot[j][i] = fmaf(wv[j], xf[i], dot[j][i]);
            }
        }
        // scoring (codes ascending -> strict < keeps lowest index on ties)
#pragma unroll
        for (int j = 0; j < 8; j++) {
            int code = cbase + ty * 8 + j;
            float cn = cnorm[code];
#pragma unroll
            for (int i = 0; i < 4; i++) {
                float t = zn[i] + cn;
                float s = fmaf(-2.f, dot[j][i], t);
                if (s < bv[i]) { bv[i] = s; bi[i] = code; }
            }
        }
    }

    __syncthreads();
#pragma unroll
    for (int i = 0; i < 4; i++) { s_val[ty][tx * 4 + i] = bv[i]; s_idx[ty][tx * 4 + i] = bi[i]; }
    __syncthreads();
    if (tid < 64) {
        float v = s_val[0][tid]; int id = s_idx[0][tid];
#pragma unroll
        for (int t = 1; t < 16; t++) {
            float v2 = s_val[t][tid]; int id2 = s_idx[t][tid];
            if (v2 < v || (v2 == v && id2 < id)) { v = v2; id = id2; }
        }
        bestv_out[blockIdx.y * NQ + zbase + tid] = v;
        besti_out[blockIdx.y * NQ + zbase + tid] = id;
    }
}

__global__ void vq_combine(const float* __restrict__ bv, const int* __restrict__ bi,
                           int* __restrict__ idx)
{
    int i = blockIdx.x * 256 + threadIdx.x;
    if (i >= NQ) return;
    float v0 = bv[i], v1 = bv[NQ + i];
    int i0 = bi[i], i1 = bi[NQ + i];
    // half 0 holds strictly smaller code indices, so ties go to half 0
    idx[i] = (v1 < v0) ? i1 : i0;
}

// =====================================================================
// gather quant = codebook[idx], accumulate commit loss sum((quant - z)^2)
// =====================================================================
__global__ __launch_bounds__(256)
void gather_commit(const float* __restrict__ cb, const float* __restrict__ z,
                   const int* __restrict__ idx, float* __restrict__ quant,
                   float* __restrict__ commit)
{
    int n = blockIdx.x;
    int t = threadIdx.x;
    int id = idx[n];
    float q = cb[(size_t)id * 256 + t];
    float zv = z[(size_t)n * 256 + t];
    quant[(size_t)n * 256 + t] = q;
    float d = q - zv; d *= d;
#pragma unroll
    for (int off = 16; off; off >>= 1) d += __shfl_down_sync(0xffffffffu, d, off);
    __shared__ float wsum[8];
    int warp = t >> 5, lane = t & 31;
    if (lane == 0) wsum[warp] = d;
    __syncthreads();
    if (t == 0) {
        float s = 0.f;
#pragma unroll
        for (int w = 0; w < 8; w++) s += wsum[w];
        atomicAdd(commit, s);
    }
}

// =====================================================================
// Final transposed conv (128 -> 3 channels), writes recon directly into d_out
// =====================================================================
__global__ __launch_bounds__(256)
void convt_out3(const float* __restrict__ in, const float* __restrict__ w,
                const float* __restrict__ bias, float* __restrict__ out)
{
    __shared__ float ws[128 * 3 * 16];   // full weight: [ic][oc][kh][kw]
    for (int i = threadIdx.x; i < 6144; i += 256) ws[i] = w[i];
    __syncthreads();

    int b = blockIdx.y, oh = blockIdx.x, ow = threadIdx.x;
    int ih0 = (oh + 1) >> 1, kh0 = (oh + 1) & 1;
    int iw0 = (ow + 1) >> 1, kw0 = (ow + 1) & 1;

    float acc0 = 0.f, acc1 = 0.f, acc2 = 0.f;
    for (int ic = 0; ic < 128; ic++) {
        const float* inp = in + ((size_t)(b * 128 + ic)) * 128 * 128;
        const float* wp = ws + ic * 48;
#pragma unroll
        for (int th = 0; th < 2; th++) {
            int ih = ih0 - th;
            if ((unsigned)ih < 128u) {
                int kh = kh0 + 2 * th;
#pragma unroll
                for (int tw = 0; tw < 2; tw++) {
                    int iw = iw0 - tw;
                    if ((unsigned)iw < 128u) {
                        int kw = kw0 + 2 * tw;
                        float v = inp[ih * 128 + iw];
                        int wk = kh * 4 + kw;
                        acc0 = fmaf(v, wp[wk], acc0);
                        acc1 = fmaf(v, wp[16 + wk], acc1);
                        acc2 = fmaf(v, wp[32 + wk], acc2);
                    }
                }
            }
        }
    }
    size_t ob = ((size_t)(b * 3) * 256 + oh) * 256 + ow;
    out[ob]               = acc0 + bias[0];
    out[ob + 65536]       = acc1 + bias[1];
    out[ob + 131072]      = acc2 + bias[2];
}

// =====================================================================
// pack commit_loss + indices into d_out tail
// =====================================================================
__global__ void pack_kernel(float* __restrict__ out, const float* __restrict__ commit,
                            const int* __restrict__ idx)
{
    int i = blockIdx.x * 256 + threadIdx.x;
    if (i == 0) out[786432] = (*commit) * (1.f / 4194304.f);
    if (i < NQ) out[786433 + i] = (float)idx[i];
}

// =====================================================================
// host launcher
// =====================================================================
extern "C" void kernel_launch(void* const* d_in, const int* in_sizes, int n_in,
                              void* d_out, int out_size)
{
    const float* x        = (const float*)d_in[0];
    const float* enc_w1   = (const float*)d_in[1];
    const float* enc_b1   = (const float*)d_in[2];
    const float* enc_w2   = (const float*)d_in[3];
    const float* enc_b2   = (const float*)d_in[4];
    const float* enc_w3   = (const float*)d_in[5];
    const float* enc_b3   = (const float*)d_in[6];
    const float* qconv_w  = (const float*)d_in[7];
    const float* qconv_b  = (const float*)d_in[8];
    const float* codebook = (const float*)d_in[9];
    const float* pqconv_w = (const float*)d_in[10];
    const float* pqconv_b = (const float*)d_in[11];
    const float* dec_w1   = (const float*)d_in[12];
    const float* dec_b1   = (const float*)d_in[13];
    const float* dect_w2  = (const float*)d_in[14];
    const float* dect_b2  = (const float*)d_in[15];
    const float* dect_w3  = (const float*)d_in[16];
    const float* dect_b3  = (const float*)d_in[17];
    float* out = (float*)d_out;

    float *h1, *h2, *h3, *z, *quant, *q, *d1, *d2, *znorm, *cnorm, *bestv, *commit;
    int *besti, *idx;
    cudaGetSymbolAddress((void**)&h1, g_h1);
    cudaGetSymbolAddress((void**)&h2, g_h2);
    cudaGetSymbolAddress((void**)&h3, g_h3);
    cudaGetSymbolAddress((void**)&z, g_z);
    cudaGetSymbolAddress((void**)&quant, g_quant);
    cudaGetSymbolAddress((void**)&q, g_q);
    cudaGetSymbolAddress((void**)&d1, g_d1);
    cudaGetSymbolAddress((void**)&d2, g_d2);
    cudaGetSymbolAddress((void**)&znorm, g_znorm);
    cudaGetSymbolAddress((void**)&cnorm, g_cnorm);
    cudaGetSymbolAddress((void**)&bestv, g_bestv);
    cudaGetSymbolAddress((void**)&besti, g_besti);
    cudaGetSymbolAddress((void**)&idx, g_idx);
    cudaGetSymbolAddress((void**)&commit, g_commit);

    // encoder
    conv_gemm<0,4,2,1,true ,0,0><<<dim3(256,1,4),256>>>(x,  enc_w1, enc_b1, h1, 3,  128, 256,256, 128,128, 7);
    conv_gemm<0,4,2,1,true ,0,0><<<dim3( 64,1,4),256>>>(h1, enc_w2, enc_b2, h2, 128,128, 128,128,  64, 64, 6);
    conv_gemm<0,3,1,1,false,0,0><<<dim3( 64,1,4),256>>>(h2, enc_w3, enc_b3, h3, 128,128,  64, 64,  64, 64, 6);
    conv_gemm<0,1,1,0,false,0,1><<<dim3( 64,2,4),256>>>(h3, qconv_w, qconv_b, z, 128,256,  64, 64,  64, 64, 6);

    // quantize
    rownorm_kernel<<<2048,256>>>(z, znorm, NQ);
    rownorm_kernel<<<1024,256>>>(codebook, cnorm, KCB);
    zero_commit_kernel<<<1,1>>>(commit);
    vq_argmin<<<dim3(256,2),256>>>(z, codebook, znorm, cnorm, bestv, besti);
    vq_combine<<<64,256>>>(bestv, besti, idx);
    gather_commit<<<NQ,256>>>(codebook, z, idx, quant, commit);

    // decoder
    conv_gemm<0,1,1,0,false,1,0><<<dim3( 64,1,4),256>>>(quant, pqconv_w, pqconv_b, q, 256,128, 64,64, 64,64, 6);
    conv_gemm<0,3,1,1,true ,0,0><<<dim3( 64,1,4),256>>>(q,  dec_w1, dec_b1, d1, 128,128, 64,64,  64, 64, 6);
    conv_gemm<2,4,2,1,true ,0,0><<<dim3(256,1,4),256>>>(d1, dect_w2, dect_b2, d2, 128,128, 64,64, 128,128, 7);
    convt_out3<<<dim3(256,4),256>>>(d2, dect_w3, dect_b3, out);

    pack_kernel<<<64,256>>>(out, commit, idx);

    (void)in_sizes; (void)n_in; (void)out_size;
}

// round 3
// speedup vs baseline: 2.0058x; 2.0058x over previous
#include <cuda_runtime.h>
#include <cuda_bf16.h>
#include <cstdint>

// ---------------- problem constants ----------------
#define BATCH 4
#define NQ    16384          // 4 * 64 * 64 latent vectors
#define EDIM  256
#define KCB   8192
#define KP    768            // packed K' = 3 * 256

// ---------------- scratch (static device memory; no allocation) ----------------
__device__ float g_h1[4 * 128 * 128 * 128];
__device__ float g_h2[4 * 128 * 64 * 64];
__device__ float g_h3[4 * 128 * 64 * 64];
__device__ float g_z[NQ * EDIM];          // [n][e]
__device__ float g_quant[NQ * EDIM];      // [n][e]
__device__ float g_q[4 * 128 * 64 * 64];
__device__ float g_d1[4 * 128 * 64 * 64];
__device__ float g_d2[4 * 128 * 128 * 128];
__device__ float g_znorm[NQ];
__device__ float g_cnorm[KCB];
__device__ int   g_idx[NQ];
__device__ float g_commit;
// bf16 packed split buffers for the VQ GEMM
__device__ __nv_bfloat16 g_apk[(size_t)NQ * KP];    // [q][zh | zl | zh]
__device__ __nv_bfloat16 g_bpk[(size_t)KCB * KP];   // [c][ch | ch | cl]
__device__ float g_bv8[8 * NQ];
__device__ int   g_bi8[8 * NQ];

// =====================================================================
// Generic implicit-GEMM conv kernel (unchanged from R1 — passing).
// =====================================================================
template<int MODE, int KK, int S, int P, bool RELU, int INL, int OUTL>
__global__ __launch_bounds__(256)
void conv_gemm(const float* __restrict__ in, const float* __restrict__ w,
               const float* __restrict__ bias, float* __restrict__ out,
               int Cin, int Cout, int Hin, int Win, int Hout, int Wout,
               int woutShift)
{
    const int R = (MODE == 2) ? Cin * 4 : Cin * KK * KK;
    const int b = blockIdx.z;
    const int oc0 = blockIdx.y * 128;

    int pxbase = 0, oh_fixed = 0, par = 0;
    if (MODE == 2) { oh_fixed = blockIdx.x >> 1; par = blockIdx.x & 1; }
    else           { pxbase = blockIdx.x * 64; }

    __shared__ float ws[16][128];
    __shared__ float xs[16][68];

    const int tid = threadIdx.x;
    const int tx = tid & 15;
    const int ty = tid >> 4;

    float acc[8][4];
#pragma unroll
    for (int j = 0; j < 8; j++)
#pragma unroll
        for (int i = 0; i < 4; i++) acc[j][i] = 0.f;

    for (int r0 = 0; r0 < R; r0 += 16) {
        __syncthreads();
        {
            int row = tid >> 1;
            int half = tid & 1;
            int oc = oc0 + row;
#pragma unroll
            for (int i = 0; i < 8; i++) {
                int r = r0 + half * 8 + i;
                float v = 0.f;
                if (r < R) {
                    if (MODE == 2) {
                        int ic = r >> 2, t = r & 3, th = t >> 1, tw = t & 1;
                        int kh = ((oh_fixed + 1) & 1) + 2 * th;
                        int kw = (1 - par) + 2 * tw;
                        v = w[((ic * Cout + oc) * 4 + kh) * 4 + kw];
                    } else {
                        v = w[oc * R + r];
                    }
                }
                ws[half * 8 + i][row] = v;
            }
        }
#pragma unroll
        for (int i2 = 0; i2 < 4; i2++) {
            int li = tid + i2 * 256;
            int r, p;
            if (INL == 1) { r = li & 15; p = li >> 4; }
            else          { r = li >> 6; p = li & 63; }
            int rr = r0 + r;
            float v = 0.f;
            if (rr < R) {
                if (MODE == 2) {
                    int ic = rr >> 2, t = rr & 3, th = t >> 1, tw = t & 1;
                    int ow = par + 2 * p;
                    int ih = ((oh_fixed + 1) >> 1) - th;
                    int iw = ((ow + 1) >> 1) - tw;
                    if ((unsigned)ih < (unsigned)Hin && (unsigned)iw < (unsigned)Win)
                        v = in[((b * Cin + ic) * Hin + ih) * Win + iw];
                } else if (INL == 1) {
                    int n = b * (Hout * Wout) + pxbase + p;
                    v = in[n * Cin + rr];
                } else {
                    int ic = rr / (KK * KK);
                    int kr = rr - ic * KK * KK;
                    int kh = kr / KK, kw = kr - kh * KK;
                    int px = pxbase + p;
                    int oh = px >> woutShift;
                    int ow = px & (Wout - 1);
                    int ih = oh * S + kh - P;
                    int iw = ow * S + kw - P;
                    if ((unsigned)ih < (unsigned)Hin && (unsigned)iw < (unsigned)Win)
                        v = in[((b * Cin + ic) * Hin + ih) * Win + iw];
                }
            }
            xs[r][p] = v;
        }
        __syncthreads();
#pragma unroll
        for (int k = 0; k < 16; k++) {
            float4 xv = *reinterpret_cast<const float4*>(&xs[k][tx * 4]);
            float4 w0 = *reinterpret_cast<const float4*>(&ws[k][ty * 8]);
            float4 w1 = *reinterpret_cast<const float4*>(&ws[k][ty * 8 + 4]);
            float wv[8] = {w0.x, w0.y, w0.z, w0.w, w1.x, w1.y, w1.z, w1.w};
            float xf[4] = {xv.x, xv.y, xv.z, xv.w};
#pragma unroll
            for (int j = 0; j < 8; j++)
#pragma unroll
                for (int i = 0; i < 4; i++)
                    acc[j][i] = fmaf(wv[j], xf[i], acc[j][i]);
        }
    }

#pragma unroll
    for (int j = 0; j < 8; j++) {
        int oc = oc0 + ty * 8 + j;
        float bv = bias[oc];
#pragma unroll
        for (int i = 0; i < 4; i++) {
            float v = acc[j][i] + bv;
            if (RELU) v = fmaxf(v, 0.f);
            if (MODE == 2) {
                int ow = par + 2 * (tx * 4 + i);
                out[((b * Cout + oc) * Hout + oh_fixed) * Wout + ow] = v;
            } else if (OUTL == 1) {
                int n = b * (Hout * Wout) + pxbase + tx * 4 + i;
                out[n * Cout + oc] = v;
            } else {
                out[(b * Cout + oc) * (Hout * Wout) + pxbase + tx * 4 + i] = v;
            }
        }
    }
}

// =====================================================================
// row squared-norm over 256-wide rows
// =====================================================================
__global__ void rownorm_kernel(const float* __restrict__ v, float* __restrict__ outn, int rows)
{
    int warp = threadIdx.x >> 5, lane = threadIdx.x & 31;
    int n = blockIdx.x * 8 + warp;
    if (n >= rows) return;
    const float* p = v + (size_t)n * 256;
    float s = 0.f;
#pragma unroll
    for (int k = 0; k < 8; k++) { float x = p[lane + 32 * k]; s = fmaf(x, x, s); }
#pragma unroll
    for (int off = 16; off; off >>= 1) s += __shfl_down_sync(0xffffffffu, s, off);
    if (lane == 0) outn[n] = s;
}

__global__ void zero_commit_kernel(float* c) { *c = 0.f; }

// =====================================================================
// bf16 split-pack kernels: A' = [zh, zl, zh], B' = [ch, ch, cl]
// =====================================================================
__global__ void pack_z_bf16(const float* __restrict__ z, __nv_bfloat16* __restrict__ A)
{
    int i = blockIdx.x * 256 + threadIdx.x;       // over NQ*256
    int q = i >> 8, k = i & 255;
    float x = z[i];
    __nv_bfloat16 h = __float2bfloat16(x);
    __nv_bfloat16 l = __float2bfloat16(x - __bfloat162float(h));
    size_t base = (size_t)q * KP;
    A[base + k] = h;
    A[base + 256 + k] = l;
    A[base + 512 + k] = h;
}

__global__ void pack_c_bf16(const float* __restrict__ c, __nv_bfloat16* __restrict__ B)
{
    int i = blockIdx.x * 256 + threadIdx.x;       // over KCB*256
    int q = i >> 8, k = i & 255;
    float x = c[i];
    __nv_bfloat16 h = __float2bfloat16(x);
    __nv_bfloat16 l = __float2bfloat16(x - __bfloat162float(h));
    size_t base = (size_t)q * KP;
    B[base + k] = h;
    B[base + 256 + k] = h;
    B[base + 512 + k] = l;
}

// =====================================================================
// VQ GEMM + fused argmin via mma.sync bf16 (legacy tensor path, sm_80+)
// CTA: 128 queries x 128 codes, K'=768. Grid: (128 M-tiles, 8 N-groups).
// Each CTA loops its group's 8 n-tiles of 128 codes.
// =====================================================================
#define CP16(dst, src) \
    asm volatile("cp.async.cg.shared.global [%0], [%1], 16;" :: "r"(dst), "l"(src) : "memory")
#define CP_COMMIT() asm volatile("cp.async.commit_group;" ::: "memory")
#define CP_WAIT1()  asm volatile("cp.async.wait_group 1;" ::: "memory")
#define CP_WAIT0()  asm volatile("cp.async.wait_group 0;" ::: "memory")

__device__ __forceinline__ uint32_t s2u(const void* p)
{
    uint32_t a;
    asm("{ .reg .u64 t; cvta.to.shared.u64 t, %1; cvt.u32.u64 %0, t; }" : "=r"(a) : "l"(p));
    return a;
}

__device__ __forceinline__ void mma_bf16(float* c, const uint32_t* a, const uint32_t* b)
{
    asm volatile(
        "mma.sync.aligned.m16n8k16.row.col.f32.bf16.bf16.f32 "
        "{%0,%1,%2,%3}, {%4,%5,%6,%7}, {%8,%9}, {%0,%1,%2,%3};"
        : "+f"(c[0]), "+f"(c[1]), "+f"(c[2]), "+f"(c[3])
        : "r"(a[0]), "r"(a[1]), "r"(a[2]), "r"(a[3]), "r"(b[0]), "r"(b[1]));
}

#define LDA 40          // padded row stride (elements) -> conflict-free
#define BUFB (128 * LDA * 2)   // bytes per stage buffer

__global__ __launch_bounds__(256)
void vq_mma(const __nv_bfloat16* __restrict__ Apk, const __nv_bfloat16* __restrict__ Bpk,
            const float* __restrict__ znorm, const float* __restrict__ cnorm,
            float* __restrict__ bv8, int* __restrict__ bi8)
{
    __shared__ __align__(16) __nv_bfloat16 sA[2][128 * LDA];
    __shared__ __align__(16) __nv_bfloat16 sB[2][128 * LDA];
    __shared__ float znS[128], cnS[128];
    __shared__ float redV[2][128];
    __shared__ int   redI[2][128];

    const int tid = threadIdx.x;
    const int lane = tid & 31, wid = tid >> 5;
    const int wm = wid & 3, wn = wid >> 2;     // warp tile: rows wm*32.., cols wn*64..
    const int lr = lane >> 2, lc = lane & 3;
    const int qbase = blockIdx.x * 128;
    const int gbase = blockIdx.y * 1024;

    if (tid < 128) znS[tid] = znorm[qbase + tid];
    __syncthreads();
    float znr[4];
#pragma unroll
    for (int s = 0; s < 4; s++)
        znr[s] = znS[wm * 32 + (s >> 1) * 16 + lr + (s & 1) * 8];

    float bestv[4] = {3.4e38f, 3.4e38f, 3.4e38f, 3.4e38f};
    int   besti[4] = {0, 0, 0, 0};

    float acc[2][8][4];
#pragma unroll
    for (int mf = 0; mf < 2; mf++)
#pragma unroll
        for (int nf = 0; nf < 8; nf++)
#pragma unroll
            for (int e = 0; e < 4; e++) acc[mf][nf][e] = 0.f;

    const int srow = tid >> 1;
    const __nv_bfloat16* asrc = Apk + (size_t)(qbase + srow) * KP + (tid & 1) * 16;
    const uint32_t saA = s2u(sA) + srow * (LDA * 2) + (tid & 1) * 32;
    const uint32_t saB = s2u(sB) + srow * (LDA * 2) + (tid & 1) * 32;

    for (int nt = 0; nt < 8; nt++) {
        const __nv_bfloat16* bsrc =
            Bpk + (size_t)(gbase + nt * 128 + srow) * KP + (tid & 1) * 16;
        if (tid < 128) cnS[tid] = cnorm[gbase + nt * 128 + tid];

        // prologue: stage chunk 0 into buffer 0
        CP16(saA, asrc);      CP16(saA + 16, asrc + 8);
        CP16(saB, bsrc);      CP16(saB + 16, bsrc + 8);
        CP_COMMIT();

        for (int kc = 0; kc < 24; kc++) {
            if (kc + 1 < 24) {
                const uint32_t nb = (uint32_t)((kc + 1) & 1) * BUFB;
                const __nv_bfloat16* a2 = asrc + (kc + 1) * 32;
                const __nv_bfloat16* b2 = bsrc + (kc + 1) * 32;
                CP16(saA + nb, a2);      CP16(saA + nb + 16, a2 + 8);
                CP16(saB + nb, b2);      CP16(saB + nb + 16, b2 + 8);
                CP_COMMIT();
                CP_WAIT1();
            } else {
                CP_WAIT0();
            }
            __syncthreads();

            const int buf = kc & 1;
#pragma unroll
            for (int ks = 0; ks < 2; ks++) {
                const int k0 = ks * 16 + lc * 2;
                uint32_t a[2][4], b[8][2];
#pragma unroll
                for (int mf = 0; mf < 2; mf++) {
                    int r = wm * 32 + mf * 16 + lr;
                    a[mf][0] = *(const uint32_t*)&sA[buf][r * LDA + k0];
                    a[mf][1] = *(const uint32_t*)&sA[buf][(r + 8) * LDA + k0];
                    a[mf][2] = *(const uint32_t*)&sA[buf][r * LDA + k0 + 8];
                    a[mf][3] = *(const uint32_t*)&sA[buf][(r + 8) * LDA + k0 + 8];
                }
#pragma unroll
                for (int nf = 0; nf < 8; nf++) {
                    int cr = wn * 64 + nf * 8 + lr;
                    b[nf][0] = *(const uint32_t*)&sB[buf][cr * LDA + k0];
                    b[nf][1] = *(const uint32_t*)&sB[buf][cr * LDA + k0 + 8];
                }
#pragma unroll
                for (int mf = 0; mf < 2; mf++)
#pragma unroll
                    for (int nf = 0; nf < 8; nf++)
                        mma_bf16(acc[mf][nf], a[mf], b[nf]);
            }
            __syncthreads();
        }

        // ---- epilogue: score + per-thread argmin, reset acc ----
#pragma unroll
        for (int mf = 0; mf < 2; mf++)
#pragma unroll
            for (int nf = 0; nf < 8; nf++)
#pragma unroll
                for (int e = 0; e < 4; e++) {
                    int h = e >> 1;
                    int col = wn * 64 + nf * 8 + lc * 2 + (e & 1);
                    int slot = mf * 2 + h;
                    float t = znr[slot] + cnS[col];
                    float s = fmaf(-2.f, acc[mf][nf][e], t);
                    int code = gbase + nt * 128 + col;
                    if (s < bestv[slot]) { bestv[slot] = s; besti[slot] = code; }
                    acc[mf][nf][e] = 0.f;
                }
        __syncthreads();
    }

    // ---- quad reduce (lanes sharing a row), then cross-warp via smem ----
#pragma unroll
    for (int s = 0; s < 4; s++) {
        float v = bestv[s]; int ix = besti[s];
#pragma unroll
        for (int off = 1; off <= 2; off <<= 1) {
            float ov = __shfl_xor_sync(0xffffffffu, v, off);
            int   oi = __shfl_xor_sync(0xffffffffu, ix, off);
            if (ov < v || (ov == v && oi < ix)) { v = ov; ix = oi; }
        }
        if (lc == 0) {
            int row = wm * 32 + (s >> 1) * 16 + lr + (s & 1) * 8;
            redV[wn][row] = v; redI[wn][row] = ix;
        }
    }
    __syncthreads();
    if (tid < 128) {
        float v = redV[0][tid]; int ix = redI[0][tid];
        float v1 = redV[1][tid]; int i1 = redI[1][tid];
        if (v1 < v || (v1 == v && i1 < ix)) { v = v1; ix = i1; }
        bv8[blockIdx.y * NQ + qbase + tid] = v;
        bi8[blockIdx.y * NQ + qbase + tid] = ix;
    }
}

__global__ void vq_combine8(const float* __restrict__ bv8, const int* __restrict__ bi8,
                            int* __restrict__ idx)
{
    int q = blockIdx.x * 256 + threadIdx.x;
    if (q >= NQ) return;
    float v = bv8[q]; int ix = bi8[q];
#pragma unroll
    for (int g = 1; g < 8; g++) {
        float v2 = bv8[g * NQ + q];
        int   i2 = bi8[g * NQ + q];
        if (v2 < v || (v2 == v && i2 < ix)) { v = v2; ix = i2; }
    }
    idx[q] = ix;
}

// =====================================================================
// gather quant = codebook[idx], accumulate commit loss sum((quant - z)^2)
// =====================================================================
__global__ __launch_bounds__(256)
void gather_commit(const float* __restrict__ cb, const float* __restrict__ z,
                   const int* __restrict__ idx, float* __restrict__ quant,
                   float* __restrict__ commit)
{
    int n = blockIdx.x;
    int t = threadIdx.x;
    int id = idx[n];
    float q = cb[(size_t)id * 256 + t];
    float zv = z[(size_t)n * 256 + t];
    quant[(size_t)n * 256 + t] = q;
    float d = q - zv; d *= d;
#pragma unroll
    for (int off = 16; off; off >>= 1) d += __shfl_down_sync(0xffffffffu, d, off);
    __shared__ float wsum[8];
    int warp = t >> 5, lane = t & 31;
    if (lane == 0) wsum[warp] = d;
    __syncthreads();
    if (t == 0) {
        float s = 0.f;
#pragma unroll
        for (int w = 0; w < 8; w++) s += wsum[w];
        atomicAdd(commit, s);
    }
}

// =====================================================================
// Final transposed conv (128 -> 3 channels) straight into d_out
// =====================================================================
__global__ __launch_bounds__(256)
void convt_out3(const float* __restrict__ in, const float* __restrict__ w,
                const float* __restrict__ bias, float* __restrict__ out)
{
    __shared__ float ws[128 * 3 * 16];
    for (int i = threadIdx.x; i < 6144; i += 256) ws[i] = w[i];
    __syncthreads();

    int b = blockIdx.y, oh = blockIdx.x, ow = threadIdx.x;
    int ih0 = (oh + 1) >> 1, kh0 = (oh + 1) & 1;
    int iw0 = (ow + 1) >> 1, kw0 = (ow + 1) & 1;

    float acc0 = 0.f, acc1 = 0.f, acc2 = 0.f;
    for (int ic = 0; ic < 128; ic++) {
        const float* inp = in + ((size_t)(b * 128 + ic)) * 128 * 128;
        const float* wp = ws + ic * 48;
#pragma unroll
        for (int th = 0; th < 2; th++) {
            int ih = ih0 - th;
            if ((unsigned)ih < 128u) {
                int kh = kh0 + 2 * th;
#pragma unroll
                for (int tw = 0; tw < 2; tw++) {
                    int iw = iw0 - tw;
                    if ((unsigned)iw < 128u) {
                        int kw = kw0 + 2 * tw;
                        float v = inp[ih * 128 + iw];
                        int wk = kh * 4 + kw;
                        acc0 = fmaf(v, wp[wk], acc0);
                        acc1 = fmaf(v, wp[16 + wk], acc1);
                        acc2 = fmaf(v, wp[32 + wk], acc2);
                    }
                }
            }
        }
    }
    size_t ob = ((size_t)(b * 3) * 256 + oh) * 256 + ow;
    out[ob]          = acc0 + bias[0];
    out[ob + 65536]  = acc1 + bias[1];
    out[ob + 131072] = acc2 + bias[2];
}

__global__ void pack_kernel(float* __restrict__ out, const float* __restrict__ commit,
                            const int* __restrict__ idx)
{
    int i = blockIdx.x * 256 + threadIdx.x;
    if (i == 0) out[786432] = (*commit) * (1.f / 4194304.f);
    if (i < NQ) out[786433 + i] = (float)idx[i];
}

// =====================================================================
// host launcher
// =====================================================================
extern "C" void kernel_launch(void* const* d_in, const int* in_sizes, int n_in,
                              void* d_out, int out_size)
{
    const float* x        = (const float*)d_in[0];
    const float* enc_w1   = (const float*)d_in[1];
    const float* enc_b1   = (const float*)d_in[2];
    const float* enc_w2   = (const float*)d_in[3];
    const float* enc_b2   = (const float*)d_in[4];
    const float* enc_w3   = (const float*)d_in[5];
    const float* enc_b3   = (const float*)d_in[6];
    const float* qconv_w  = (const float*)d_in[7];
    const float* qconv_b  = (const float*)d_in[8];
    const float* codebook = (const float*)d_in[9];
    const float* pqconv_w = (const float*)d_in[10];
    const float* pqconv_b = (const float*)d_in[11];
    const float* dec_w1   = (const float*)d_in[12];
    const float* dec_b1   = (const float*)d_in[13];
    const float* dect_w2  = (const float*)d_in[14];
    const float* dect_b2  = (const float*)d_in[15];
    const float* dect_w3  = (const float*)d_in[16];
    const float* dect_b3  = (const float*)d_in[17];
    float* out = (float*)d_out;

    float *h1, *h2, *h3, *z, *quant, *q, *d1, *d2, *znorm, *cnorm, *commit, *bv8;
    __nv_bfloat16 *apk, *bpk;
    int *idx, *bi8;
    cudaGetSymbolAddress((void**)&h1, g_h1);
    cudaGetSymbolAddress((void**)&h2, g_h2);
    cudaGetSymbolAddress((void**)&h3, g_h3);
    cudaGetSymbolAddress((void**)&z, g_z);
    cudaGetSymbolAddress((void**)&quant, g_quant);
    cudaGetSymbolAddress((void**)&q, g_q);
    cudaGetSymbolAddress((void**)&d1, g_d1);
    cudaGetSymbolAddress((void**)&d2, g_d2);
    cudaGetSymbolAddress((void**)&znorm, g_znorm);
    cudaGetSymbolAddress((void**)&cnorm, g_cnorm);
    cudaGetSymbolAddress((void**)&idx, g_idx);
    cudaGetSymbolAddress((void**)&commit, g_commit);
    cudaGetSymbolAddress((void**)&apk, g_apk);
    cudaGetSymbolAddress((void**)&bpk, g_bpk);
    cudaGetSymbolAddress((void**)&bv8, g_bv8);
    cudaGetSymbolAddress((void**)&bi8, g_bi8);

    // encoder
    conv_gemm<0,4,2,1,true ,0,0><<<dim3(256,1,4),256>>>(x,  enc_w1, enc_b1, h1, 3,  128, 256,256, 128,128, 7);
    conv_gemm<0,4,2,1,true ,0,0><<<dim3( 64,1,4),256>>>(h1, enc_w2, enc_b2, h2, 128,128, 128,128,  64, 64, 6);
    conv_gemm<0,3,1,1,false,0,0><<<dim3( 64,1,4),256>>>(h2, enc_w3, enc_b3, h3, 128,128,  64, 64,  64, 64, 6);
    conv_gemm<0,1,1,0,false,0,1><<<dim3( 64,2,4),256>>>(h3, qconv_w, qconv_b, z, 128,256,  64, 64,  64, 64, 6);

    // quantize: bf16 3-split pack + norms, then tensor-core GEMM argmin
    pack_z_bf16<<<NQ, 256>>>(z, apk);                    // NQ*256/256 = NQ blocks
    pack_c_bf16<<<KCB, 256>>>(codebook, bpk);
    rownorm_kernel<<<2048, 256>>>(z, znorm, NQ);
    rownorm_kernel<<<1024, 256>>>(codebook, cnorm, KCB);
    zero_commit_kernel<<<1, 1>>>(commit);
    vq_mma<<<dim3(128, 8), 256>>>(apk, bpk, znorm, cnorm, bv8, bi8);
    vq_combine8<<<64, 256>>>(bv8, bi8, idx);
    gather_commit<<<NQ, 256>>>(codebook, z, idx, quant, commit);

    // decoder
    conv_gemm<0,1,1,0,false,1,0><<<dim3( 64,1,4),256>>>(quant, pqconv_w, pqconv_b, q, 256,128, 64,64, 64,64, 6);
    conv_gemm<0,3,1,1,true ,0,0><<<dim3( 64,1,4),256>>>(q,  dec_w1, dec_b1, d1, 128,128, 64,64,  64, 64, 6);
    conv_gemm<2,4,2,1,true ,0,0><<<dim3(256,1,4),256>>>(d1, dect_w2, dect_b2, d2, 128,128, 64,64, 128,128, 7);
    convt_out3<<<dim3(256,4),256>>>(d2, dect_w3, dect_b3, out);

    pack_kernel<<<64, 256>>>(out, commit, idx);

    (void)in_sizes; (void)n_in; (void)out_size;
}

// round 5
// speedup vs baseline: 2.2187x; 1.1061x over previous
#include <cuda_runtime.h>
#include <cuda_bf16.h>
#include <cstdint>

// ---------------- problem constants ----------------
#define BATCH 4
#define NQ    16384
#define EDIM  256
#define KCB   8192
#define KP    768            // packed K' = 3 * 256 for VQ GEMM

// ---------------- scratch (static device memory; no allocation) ----------------
__device__ float g_h1[4 * 128 * 128 * 128];
__device__ float g_h2[4 * 128 * 64 * 64];
__device__ float g_h3[4 * 128 * 64 * 64];
__device__ float g_z[NQ * EDIM];
__device__ float g_quant[NQ * EDIM];
__device__ __nv_bfloat16 g_qh[4 * 128 * 64 * 64];
__device__ __nv_bfloat16 g_ql[4 * 128 * 64 * 64];
__device__ __nv_bfloat16 g_d1h[4 * 128 * 64 * 64];
__device__ __nv_bfloat16 g_d1l[4 * 128 * 64 * 64];
__device__ float g_d2[4 * 128 * 128 * 128];
__device__ float g_znorm[NQ];
__device__ float g_cnorm[KCB];
__device__ int   g_idx[NQ];
__device__ float g_commit;
// VQ packed split buffers
__device__ __nv_bfloat16 g_apk[(size_t)NQ * KP];
__device__ __nv_bfloat16 g_bpk[(size_t)KCB * KP];
__device__ float g_bv8[8 * NQ];
__device__ int   g_bi8[8 * NQ];
// pre-split decoder weights
__device__ __nv_bfloat16 g_wd1h[128 * 1152], g_wd1l[128 * 1152];
__device__ __nv_bfloat16 g_wt2h[4 * 128 * 512], g_wt2l[4 * 128 * 512];

__device__ __forceinline__ uint32_t s2u(const void* p)
{
    uint32_t a;
    asm("{ .reg .u64 t; cvta.to.shared.u64 t, %1; cvt.u32.u64 %0, t; }" : "=r"(a) : "l"(p));
    return a;
}

#define CP16(dst, src) \
    asm volatile("cp.async.cg.shared.global [%0], [%1], 16;" :: "r"(dst), "l"(src) : "memory")
#define CP_COMMIT() asm volatile("cp.async.commit_group;" ::: "memory")
#define CP_WAIT1()  asm volatile("cp.async.wait_group 1;" ::: "memory")
#define CP_WAIT0()  asm volatile("cp.async.wait_group 0;" ::: "memory")

__device__ __forceinline__ void mma_bf16(float* c, const uint32_t* a, const uint32_t* b)
{
    asm volatile(
        "mma.sync.aligned.m16n8k16.row.col.f32.bf16.bf16.f32 "
        "{%0,%1,%2,%3}, {%4,%5,%6,%7}, {%8,%9}, {%0,%1,%2,%3};"
        : "+f"(c[0]), "+f"(c[1]), "+f"(c[2]), "+f"(c[3])
        : "r"(a[0]), "r"(a[1]), "r"(a[2]), "r"(a[3]), "r"(b[0]), "r"(b[1]));
}

// =====================================================================
// FFMA implicit-GEMM conv — EXACT R1 arithmetic (bitwise-stable z path).
// OUTL: 0 = NCHW f32, 1 = [n][Cout] f32, 2 = bf16 split planes NCHW.
// =====================================================================
template<int KK, int S, int P, bool RELU, int INL, int OUTL>
__global__ __launch_bounds__(256)
void conv_gemm(const float* __restrict__ in, const float* __restrict__ w,
               const float* __restrict__ bias, float* __restrict__ out,
               __nv_bfloat16* __restrict__ outh, __nv_bfloat16* __restrict__ outl,
               int Cin, int Cout, int Hin, int Win, int Hout, int Wout,
               int woutShift)
{
    const int R = Cin * KK * KK;
    const int b = blockIdx.z;
    const int oc0 = blockIdx.y * 128;
    const int pxbase = blockIdx.x * 64;

    __shared__ float ws[16][128];
    __shared__ float xs[16][68];

    const int tid = threadIdx.x;
    const int tx = tid & 15;
    const int ty = tid >> 4;

    float acc[8][4];
#pragma unroll
    for (int j = 0; j < 8; j++)
#pragma unroll
        for (int i = 0; i < 4; i++) acc[j][i] = 0.f;

    for (int r0 = 0; r0 < R; r0 += 16) {
        __syncthreads();
        {
            int row = tid >> 1;
            int half = tid & 1;
            int oc = oc0 + row;
#pragma unroll
            for (int i = 0; i < 8; i++) {
                int r = r0 + half * 8 + i;
                ws[half * 8 + i][row] = (r < R) ? w[oc * R + r] : 0.f;
            }
        }
#pragma unroll
        for (int i2 = 0; i2 < 4; i2++) {
            int li = tid + i2 * 256;
            int r, p;
            if (INL == 1) { r = li & 15; p = li >> 4; }
            else          { r = li >> 6; p = li & 63; }
            int rr = r0 + r;
            float v = 0.f;
            if (rr < R) {
                if (INL == 1) {
                    int n = b * (Hout * Wout) + pxbase + p;
                    v = in[(size_t)n * Cin + rr];
                } else {
                    int ic = rr / (KK * KK);
                    int kr = rr - ic * KK * KK;
                    int kh = kr / KK, kw = kr - kh * KK;
                    int px = pxbase + p;
                    int oh = px >> woutShift;
                    int ow = px & (Wout - 1);
                    int ih = oh * S + kh - P;
                    int iw = ow * S + kw - P;
                    if ((unsigned)ih < (unsigned)Hin && (unsigned)iw < (unsigned)Win)
                        v = in[((size_t)(b * Cin + ic) * Hin + ih) * Win + iw];
                }
            }
            xs[r][p] = v;
        }
        __syncthreads();
#pragma unroll
        for (int k = 0; k < 16; k++) {
            float4 xv = *reinterpret_cast<const float4*>(&xs[k][tx * 4]);
            float4 w0 = *reinterpret_cast<const float4*>(&ws[k][ty * 8]);
            float4 w1 = *reinterpret_cast<const float4*>(&ws[k][ty * 8 + 4]);
            float wv[8] = {w0.x, w0.y, w0.z, w0.w, w1.x, w1.y, w1.z, w1.w};
            float xf[4] = {xv.x, xv.y, xv.z, xv.w};
#pragma unroll
            for (int j = 0; j < 8; j++)
#pragma unroll
                for (int i = 0; i < 4; i++)
                    acc[j][i] = fmaf(wv[j], xf[i], acc[j][i]);
        }
    }

#pragma unroll
    for (int j = 0; j < 8; j++) {
        int oc = oc0 + ty * 8 + j;
        float bv = bias[oc];
#pragma unroll
        for (int i = 0; i < 4; i++) {
            float v = acc[j][i] + bv;
            if (RELU) v = fmaxf(v, 0.f);
            if (OUTL == 1) {
                size_t n = (size_t)(b * (Hout * Wout) + pxbase + tx * 4 + i);
                out[n * Cout + oc] = v;
            } else {
                size_t addr = (size_t)(b * Cout + oc) * (Hout * Wout) + pxbase + tx * 4 + i;
                if (OUTL == 0) {
                    out[addr] = v;
                } else {
                    __nv_bfloat16 h = __float2bfloat16(v);
                    outh[addr] = h;
                    outl[addr] = __float2bfloat16(v - __bfloat162float(h));
                }
            }
        }
    }
}

// =====================================================================
// Tensor-core implicit-GEMM conv, bf16 3-term split — DECODER ONLY.
// MODE 0: normal conv (out 64x64). MODE 1: ConvTranspose k4 s2 p1
// (in 64x64 -> out 128x128, parity classes via blockIdx.y).
// OUTMODE 0: f32 NCHW.  1: bf16 split planes NCHW.
// =====================================================================
#define CLDA 40
#define ABUF 5120

template<int MODE, int KK, int S, int P, bool RELU, int OUTMODE>
__global__ __launch_bounds__(256)
void conv_mma(const __nv_bfloat16* __restrict__ xh, const __nv_bfloat16* __restrict__ xl,
              const __nv_bfloat16* __restrict__ wh_g, const __nv_bfloat16* __restrict__ wl_g,
              const float* __restrict__ bias,
              float* __restrict__ outf, __nv_bfloat16* __restrict__ outh,
              __nv_bfloat16* __restrict__ outl,
              int Cin, int Hin, int Win, int R)
{
    extern __shared__ __align__(16) char sm[];
    __nv_bfloat16* sA_h = (__nv_bfloat16*)(sm);
    __nv_bfloat16* sA_l = (__nv_bfloat16*)(sm + 20480);
    __nv_bfloat16* sB_h = (__nv_bfloat16*)(sm + 40960);
    __nv_bfloat16* sB_l = (__nv_bfloat16*)(sm + 61440);
    float* biasS = (float*)(sm + 81920);

    const int tid = threadIdx.x;
    const int lane = tid & 31, wid = tid >> 5;
    const int wm = wid & 3, wn = wid >> 2;
    const int lr = lane >> 2, lc = lane & 3;
    const int b = blockIdx.z;

    int pxbase = 0, j0 = 0, ohp = 0, owp = 0;
    const __nv_bfloat16* wh = wh_g;
    const __nv_bfloat16* wl = wl_g;
    if (MODE == 1) {
        j0 = blockIdx.x * 2;
        int cls = blockIdx.y;
        ohp = cls >> 1; owp = cls & 1;
        wh = wh_g + cls * (128 * 512);
        wl = wl_g + cls * (128 * 512);
    } else {
        pxbase = blockIdx.x * 128;
    }

    if (tid < 128) biasS[tid] = bias[tid];

    const int NC = R >> 5;

    const int boc = tid >> 1;
    const uint32_t sbBh = s2u(sB_h), sbBl = s2u(sB_l);
    const uint32_t bOff = (uint32_t)(boc * 80 + (tid & 1) * 32);
    const size_t bSrc = (size_t)boc * R + (tid & 1) * 16;

    const int kloc = tid & 31, pblk = tid >> 5;

    float acc[2][8][4];
#pragma unroll
    for (int mf = 0; mf < 2; mf++)
#pragma unroll
        for (int nf = 0; nf < 8; nf++)
#pragma unroll
            for (int e = 0; e < 4; e++) acc[mf][nf][e] = 0.f;

    __nv_bfloat16 pvh[16], pvl[16];

    auto cpB = [&](int r0, int bf) {
        uint32_t d = (uint32_t)bf * 10240;
        const __nv_bfloat16* sh = wh + bSrc + r0;
        const __nv_bfloat16* sl = wl + bSrc + r0;
        CP16(sbBh + d + bOff, sh);  CP16(sbBh + d + bOff + 16, sh + 8);
        CP16(sbBl + d + bOff, sl);  CP16(sbBl + d + bOff + 16, sl + 8);
    };

    auto ldgA = [&](int r0) {
        int r = r0 + kloc;
        if (MODE == 0) {
            int ic = r / (KK * KK);
            int rem = r - ic * KK * KK;
            int kh = rem / KK, kw = rem - kh * KK;
            int px = pxbase + pblk * 16;
            int oh = px >> 6, ow0 = px & 63;
            int ih = oh * S + kh - P;
            const size_t rowb = ((size_t)(b * Cin + ic) * Hin + ih) * Win;
            bool okh = (unsigned)ih < (unsigned)Hin;
#pragma unroll
            for (int i = 0; i < 16; i++) {
                int iw = (ow0 + i) * S + kw - P;
                bool ok = okh && (unsigned)iw < (unsigned)Win;
                pvh[i] = ok ? xh[rowb + iw] : __float2bfloat16(0.f);
                pvl[i] = ok ? xl[rowb + iw] : __float2bfloat16(0.f);
            }
        } else {
            int ic = r >> 2, th = (r >> 1) & 1, tw = r & 1;
            int j = j0 + (pblk >> 2);
            int i0 = (pblk & 3) * 16;
            int ih = j + (1 - ohp) - th;
            int iwb = i0 + (1 - owp) - tw;
            const size_t rowb = ((size_t)(b * Cin + ic) * 64 + ih) * 64;
            bool okh = (unsigned)ih < 64u;
#pragma unroll
            for (int i = 0; i < 16; i++) {
                int iw = iwb + i;
                bool ok = okh && (unsigned)iw < 64u;
                pvh[i] = ok ? xh[rowb + iw] : __float2bfloat16(0.f);
                pvl[i] = ok ? xl[rowb + iw] : __float2bfloat16(0.f);
            }
        }
    };

    auto stsA = [&](int bf) {
        int base = bf * ABUF + kloc;
#pragma unroll
        for (int i = 0; i < 16; i++) {
            int p = pblk * 16 + i;
            sA_h[base + p * CLDA] = pvh[i];
            sA_l[base + p * CLDA] = pvl[i];
        }
    };

    auto domma = [&](int bf) {
        const int off = bf * ABUF;
#pragma unroll
        for (int ks = 0; ks < 2; ks++) {
            const int k0 = ks * 16 + lc * 2;
            uint32_t ah[2][4], al[2][4];
#pragma unroll
            for (int mf = 0; mf < 2; mf++) {
                int r1 = wm * 32 + mf * 16 + lr;
                ah[mf][0] = *(const uint32_t*)&sA_h[off + r1 * CLDA + k0];
                ah[mf][1] = *(const uint32_t*)&sA_h[off + (r1 + 8) * CLDA + k0];
                ah[mf][2] = *(const uint32_t*)&sA_h[off + r1 * CLDA + k0 + 8];
                ah[mf][3] = *(const uint32_t*)&sA_h[off + (r1 + 8) * CLDA + k0 + 8];
                al[mf][0] = *(const uint32_t*)&sA_l[off + r1 * CLDA + k0];
                al[mf][1] = *(const uint32_t*)&sA_l[off + (r1 + 8) * CLDA + k0];
                al[mf][2] = *(const uint32_t*)&sA_l[off + r1 * CLDA + k0 + 8];
                al[mf][3] = *(const uint32_t*)&sA_l[off + (r1 + 8) * CLDA + k0 + 8];
            }
#pragma unroll
            for (int nf = 0; nf < 8; nf++) {
                int cr = wn * 64 + nf * 8 + lr;
                uint32_t bh[2], bl[2];
                bh[0] = *(const uint32_t*)&sB_h[off + cr * CLDA + k0];
                bh[1] = *(const uint32_t*)&sB_h[off + cr * CLDA + k0 + 8];
                bl[0] = *(const uint32_t*)&sB_l[off + cr * CLDA + k0];
                bl[1] = *(const uint32_t*)&sB_l[off + cr * CLDA + k0 + 8];
#pragma unroll
                for (int mf = 0; mf < 2; mf++) {
                    mma_bf16(acc[mf][nf], ah[mf], bh);
                    mma_bf16(acc[mf][nf], al[mf], bh);
                    mma_bf16(acc[mf][nf], ah[mf], bl);
                }
            }
        }
    };

    cpB(0, 0); CP_COMMIT();
    ldgA(0); stsA(0);
    for (int kc = 0; kc < NC; kc++) {
        const int bf = kc & 1;
        const bool nxt = (kc + 1 < NC);
        if (nxt) {
            cpB((kc + 1) * 32, bf ^ 1); CP_COMMIT();
            ldgA((kc + 1) * 32);
            CP_WAIT1();
        } else {
            CP_WAIT0();
        }
        __syncthreads();
        domma(bf);
        if (nxt) stsA(bf ^ 1);
        __syncthreads();
    }

#pragma unroll
    for (int mf = 0; mf < 2; mf++)
#pragma unroll
        for (int nf = 0; nf < 8; nf++)
#pragma unroll
            for (int e = 0; e < 4; e++) {
                int row = wm * 32 + mf * 16 + lr + (e >> 1) * 8;
                int oc = wn * 64 + nf * 8 + lc * 2 + (e & 1);
                float v = acc[mf][nf][e] + biasS[oc];
                if (RELU) v = fmaxf(v, 0.f);
                size_t addr;
                if (MODE == 0) {
                    int px = pxbase + row;
                    addr = ((size_t)(b * 128 + oc) * 64 + (px >> 6)) * 64 + (px & 63);
                } else {
                    int oh = (1 - ohp) + 2 * (j0 + (row >> 6));
                    int ow = (1 - owp) + 2 * (row & 63);
                    addr = ((size_t)(b * 128 + oc) * 128 + oh) * 128 + ow;
                }
                if (OUTMODE == 0) {
                    outf[addr] = v;
                } else {
                    __nv_bfloat16 h = __float2bfloat16(v);
                    outh[addr] = h;
                    outl[addr] = __float2bfloat16(v - __bfloat162float(h));
                }
            }
}

// =====================================================================
// weight split kernels (decoder only)
// =====================================================================
__global__ void wsplit(const float* __restrict__ w, __nv_bfloat16* __restrict__ wh,
                       __nv_bfloat16* __restrict__ wl, int n)
{
    int i = blockIdx.x * 256 + threadIdx.x;
    if (i >= n) return;
    float x = w[i];
    __nv_bfloat16 h = __float2bfloat16(x);
    wh[i] = h;
    wl[i] = __float2bfloat16(x - __bfloat162float(h));
}

__global__ void pack_wt2(const float* __restrict__ w, __nv_bfloat16* __restrict__ wh,
                         __nv_bfloat16* __restrict__ wl)
{
    int i = blockIdx.x * 256 + threadIdx.x;      // over 4*128*512
    int cls = i >> 16;
    int oc = (i >> 9) & 127;
    int r = i & 511;
    int ohp = cls >> 1, owp = cls & 1;
    int ic = r >> 2, th = (r >> 1) & 1, tw = r & 1;
    float x = w[((ic * 128 + oc) * 4 + ohp + 2 * th) * 4 + owp + 2 * tw];
    __nv_bfloat16 h = __float2bfloat16(x);
    wh[i] = h;
    wl[i] = __float2bfloat16(x - __bfloat162float(h));
}

// =====================================================================
// row squared-norm (exact R1 arithmetic)
// =====================================================================
__global__ void rownorm_kernel(const float* __restrict__ v, float* __restrict__ outn, int rows)
{
    int warp = threadIdx.x >> 5, lane = threadIdx.x & 31;
    int n = blockIdx.x * 8 + warp;
    if (n >= rows) return;
    const float* p = v + (size_t)n * 256;
    float s = 0.f;
#pragma unroll
    for (int k = 0; k < 8; k++) { float x = p[lane + 32 * k]; s = fmaf(x, x, s); }
#pragma unroll
    for (int off = 16; off; off >>= 1) s += __shfl_down_sync(0xffffffffu, s, off);
    if (lane == 0) outn[n] = s;
}

__global__ void zero_commit_kernel(float* c) { *c = 0.f; }

// =====================================================================
// VQ pack kernels (exact R3)
// =====================================================================
__global__ void pack_z_bf16(const float* __restrict__ z, __nv_bfloat16* __restrict__ A)
{
    int i = blockIdx.x * 256 + threadIdx.x;
    int q = i >> 8, k = i & 255;
    float x = z[i];
    __nv_bfloat16 h = __float2bfloat16(x);
    __nv_bfloat16 l = __float2bfloat16(x - __bfloat162float(h));
    size_t base = (size_t)q * KP;
    A[base + k] = h;
    A[base + 256 + k] = l;
    A[base + 512 + k] = h;
}

__global__ void pack_c_bf16(const float* __restrict__ c, __nv_bfloat16* __restrict__ B)
{
    int i = blockIdx.x * 256 + threadIdx.x;
    int q = i >> 8, k = i & 255;
    float x = c[i];
    __nv_bfloat16 h = __float2bfloat16(x);
    __nv_bfloat16 l = __float2bfloat16(x - __bfloat162float(h));
    size_t base = (size_t)q * KP;
    B[base + k] = h;
    B[base + 256 + k] = h;
    B[base + 512 + k] = l;
}

// =====================================================================
// VQ GEMM + fused argmin (exact R3 — passing)
// =====================================================================
#define LDA 40
#define BUFB (128 * LDA * 2)

__global__ __launch_bounds__(256)
void vq_mma(const __nv_bfloat16* __restrict__ Apk, const __nv_bfloat16* __restrict__ Bpk,
            const float* __restrict__ znorm, const float* __restrict__ cnorm,
            float* __restrict__ bv8, int* __restrict__ bi8)
{
    __shared__ __align__(16) __nv_bfloat16 sA[2][128 * LDA];
    __shared__ __align__(16) __nv_bfloat16 sB[2][128 * LDA];
    __shared__ float znS[128], cnS[128];
    __shared__ float redV[2][128];
    __shared__ int   redI[2][128];

    const int tid = threadIdx.x;
    const int lane = tid & 31, wid = tid >> 5;
    const int wm = wid & 3, wn = wid >> 2;
    const int lr = lane >> 2, lc = lane & 3;
    const int qbase = blockIdx.x * 128;
    const int gbase = blockIdx.y * 1024;

    if (tid < 128) znS[tid] = znorm[qbase + tid];
    __syncthreads();
    float znr[4];
#pragma unroll
    for (int s = 0; s < 4; s++)
        znr[s] = znS[wm * 32 + (s >> 1) * 16 + lr + (s & 1) * 8];

    float bestv[4] = {3.4e38f, 3.4e38f, 3.4e38f, 3.4e38f};
    int   besti[4] = {0, 0, 0, 0};

    float acc[2][8][4];
#pragma unroll
    for (int mf = 0; mf < 2; mf++)
#pragma unroll
        for (int nf = 0; nf < 8; nf++)
#pragma unroll
            for (int e = 0; e < 4; e++) acc[mf][nf][e] = 0.f;

    const int srow = tid >> 1;
    const __nv_bfloat16* asrc = Apk + (size_t)(qbase + srow) * KP + (tid & 1) * 16;
    const uint32_t saA = s2u(sA) + srow * (LDA * 2) + (tid & 1) * 32;
    const uint32_t saB = s2u(sB) + srow * (LDA * 2) + (tid & 1) * 32;

    for (int nt = 0; nt < 8; nt++) {
        const __nv_bfloat16* bsrc =
            Bpk + (size_t)(gbase + nt * 128 + srow) * KP + (tid & 1) * 16;
        if (tid < 128) cnS[tid] = cnorm[gbase + nt * 128 + tid];

        CP16(saA, asrc);      CP16(saA + 16, asrc + 8);
        CP16(saB, bsrc);      CP16(saB + 16, bsrc + 8);
        CP_COMMIT();

        for (int kc = 0; kc < 24; kc++) {
            if (kc + 1 < 24) {
                const uint32_t nb = (uint32_t)((kc + 1) & 1) * BUFB;
                const __nv_bfloat16* a2 = asrc + (kc + 1) * 32;
                const __nv_bfloat16* b2 = bsrc + (kc + 1) * 32;
                CP16(saA + nb, a2);      CP16(saA + nb + 16, a2 + 8);
                CP16(saB + nb, b2);      CP16(saB + nb + 16, b2 + 8);
                CP_COMMIT();
                CP_WAIT1();
            } else {
                CP_WAIT0();
            }
            __syncthreads();

            const int buf = kc & 1;
#pragma unroll
            for (int ks = 0; ks < 2; ks++) {
                const int k0 = ks * 16 + lc * 2;
                uint32_t a[2][4], b[8][2];
#pragma unroll
                for (int mf = 0; mf < 2; mf++) {
                    int r = wm * 32 + mf * 16 + lr;
                    a[mf][0] = *(const uint32_t*)&sA[buf][r * LDA + k0];
                    a[mf][1] = *(const uint32_t*)&sA[buf][(r + 8) * LDA + k0];
                    a[mf][2] = *(const uint32_t*)&sA[buf][r * LDA + k0 + 8];
                    a[mf][3] = *(const uint32_t*)&sA[buf][(r + 8) * LDA + k0 + 8];
                }
#pragma unroll
                for (int nf = 0; nf < 8; nf++) {
                    int cr = wn * 64 + nf * 8 + lr;
                    b[nf][0] = *(const uint32_t*)&sB[buf][cr * LDA + k0];
                    b[nf][1] = *(const uint32_t*)&sB[buf][cr * LDA + k0 + 8];
                }
#pragma unroll
                for (int mf = 0; mf < 2; mf++)
#pragma unroll
                    for (int nf = 0; nf < 8; nf++)
                        mma_bf16(acc[mf][nf], a[mf], b[nf]);
            }
            __syncthreads();
        }

#pragma unroll
        for (int mf = 0; mf < 2; mf++)
#pragma unroll
            for (int nf = 0; nf < 8; nf++)
#pragma unroll
                for (int e = 0; e < 4; e++) {
                    int h = e >> 1;
                    int col = wn * 64 + nf * 8 + lc * 2 + (e & 1);
                    int slot = mf * 2 + h;
                    float t = znr[slot] + cnS[col];
                    float s = fmaf(-2.f, acc[mf][nf][e], t);
                    int code = gbase + nt * 128 + col;
                    if (s < bestv[slot]) { bestv[slot] = s; besti[slot] = code; }
                    acc[mf][nf][e] = 0.f;
                }
        __syncthreads();
    }

#pragma unroll
    for (int s = 0; s < 4; s++) {
        float v = bestv[s]; int ix = besti[s];
#pragma unroll
        for (int off = 1; off <= 2; off <<= 1) {
            float ov = __shfl_xor_sync(0xffffffffu, v, off);
            int   oi = __shfl_xor_sync(0xffffffffu, ix, off);
            if (ov < v || (ov == v && oi < ix)) { v = ov; ix = oi; }
        }
        if (lc == 0) {
            int row = wm * 32 + (s >> 1) * 16 + lr + (s & 1) * 8;
            redV[wn][row] = v; redI[wn][row] = ix;
        }
    }
    __syncthreads();
    if (tid < 128) {
        float v = redV[0][tid]; int ix = redI[0][tid];
        float v1 = redV[1][tid]; int i1 = redI[1][tid];
        if (v1 < v || (v1 == v && i1 < ix)) { v = v1; ix = i1; }
        bv8[blockIdx.y * NQ + qbase + tid] = v;
        bi8[blockIdx.y * NQ + qbase + tid] = ix;
    }
}

__global__ void vq_combine8(const float* __restrict__ bv8, const int* __restrict__ bi8,
                            int* __restrict__ idx)
{
    int q = blockIdx.x * 256 + threadIdx.x;
    if (q >= NQ) return;
    float v = bv8[q]; int ix = bi8[q];
#pragma unroll
    for (int g = 1; g < 8; g++) {
        float v2 = bv8[g * NQ + q];
        int   i2 = bi8[g * NQ + q];
        if (v2 < v || (v2 == v && i2 < ix)) { v = v2; ix = i2; }
    }
    idx[q] = ix;
}

// =====================================================================
// gather quant = codebook[idx], commit loss
// =====================================================================
__global__ __launch_bounds__(256)
void gather_commit(const float* __restrict__ cb, const float* __restrict__ z,
                   const int* __restrict__ idx, float* __restrict__ quant,
                   float* __restrict__ commit)
{
    int n = blockIdx.x;
    int t = threadIdx.x;
    int id = idx[n];
    float q = cb[(size_t)id * 256 + t];
    float zv = z[(size_t)n * 256 + t];
    quant[(size_t)n * 256 + t] = q;
    float d = q - zv; d *= d;
#pragma unroll
    for (int off = 16; off; off >>= 1) d += __shfl_down_sync(0xffffffffu, d, off);
    __shared__ float wsum[8];
    int warp = t >> 5, lane = t & 31;
    if (lane == 0) wsum[warp] = d;
    __syncthreads();
    if (t == 0) {
        float s = 0.f;
#pragma unroll
        for (int w = 0; w < 8; w++) s += wsum[w];
        atomicAdd(commit, s);
    }
}

// =====================================================================
// Final transposed conv (128 -> 3 channels) straight into d_out
// =====================================================================
__global__ __launch_bounds__(256)
void convt_out3(const float* __restrict__ in, const float* __restrict__ w,
                const float* __restrict__ bias, float* __restrict__ out)
{
    __shared__ float ws[128 * 3 * 16];
    for (int i = threadIdx.x; i < 6144; i += 256) ws[i] = w[i];
    __syncthreads();

    int b = blockIdx.y, oh = blockIdx.x, ow = threadIdx.x;
    int ih0 = (oh + 1) >> 1, kh0 = (oh + 1) & 1;
    int iw0 = (ow + 1) >> 1, kw0 = (ow + 1) & 1;

    float acc0 = 0.f, acc1 = 0.f, acc2 = 0.f;
    for (int ic = 0; ic < 128; ic++) {
        const float* inp = in + ((size_t)(b * 128 + ic)) * 128 * 128;
        const float* wp = ws + ic * 48;
#pragma unroll
        for (int th = 0; th < 2; th++) {
            int ih = ih0 - th;
            if ((unsigned)ih < 128u) {
                int kh = kh0 + 2 * th;
#pragma unroll
                for (int tw = 0; tw < 2; tw++) {
                    int iw = iw0 - tw;
                    if ((unsigned)iw < 128u) {
                        int kw = kw0 + 2 * tw;
                        float v = inp[ih * 128 + iw];
                        int wk = kh * 4 + kw;
                        acc0 = fmaf(v, wp[wk], acc0);
                        acc1 = fmaf(v, wp[16 + wk], acc1);
                        acc2 = fmaf(v, wp[32 + wk], acc2);
                    }
                }
            }
        }
    }
    size_t ob = ((size_t)(b * 3) * 256 + oh) * 256 + ow;
    out[ob]          = acc0 + bias[0];
    out[ob + 65536]  = acc1 + bias[1];
    out[ob + 131072] = acc2 + bias[2];
}

__global__ void pack_kernel(float* __restrict__ out, const float* __restrict__ commit,
                            const int* __restrict__ idx)
{
    int i = blockIdx.x * 256 + threadIdx.x;
    if (i == 0) out[786432] = (*commit) * (1.f / 4194304.f);
    if (i < NQ) out[786433 + i] = (float)idx[i];
}

// =====================================================================
// host launcher
// =====================================================================
#define CMMA_SMEM 82432

extern "C" void kernel_launch(void* const* d_in, const int* in_sizes, int n_in,
                              void* d_out, int out_size)
{
    const float* x        = (const float*)d_in[0];
    const float* enc_w1   = (const float*)d_in[1];
    const float* enc_b1   = (const float*)d_in[2];
    const float* enc_w2   = (const float*)d_in[3];
    const float* enc_b2   = (const float*)d_in[4];
    const float* enc_w3   = (const float*)d_in[5];
    const float* enc_b3   = (const float*)d_in[6];
    const float* qconv_w  = (const float*)d_in[7];
    const float* qconv_b  = (const float*)d_in[8];
    const float* codebook = (const float*)d_in[9];
    const float* pqconv_w = (const float*)d_in[10];
    const float* pqconv_b = (const float*)d_in[11];
    const float* dec_w1   = (const float*)d_in[12];
    const float* dec_b1   = (const float*)d_in[13];
    const float* dect_w2  = (const float*)d_in[14];
    const float* dect_b2  = (const float*)d_in[15];
    const float* dect_w3  = (const float*)d_in[16];
    const float* dect_b3  = (const float*)d_in[17];
    float* out = (float*)d_out;

    float *h1, *h2, *h3, *z, *quant, *d2, *znorm, *cnorm, *commit, *bv8;
    __nv_bfloat16 *qh, *ql, *d1h, *d1l, *apk, *bpk;
    __nv_bfloat16 *wd1h, *wd1l, *wt2h, *wt2l;
    int *idx, *bi8;
    cudaGetSymbolAddress((void**)&h1, g_h1);
    cudaGetSymbolAddress((void**)&h2, g_h2);
    cudaGetSymbolAddress((void**)&h3, g_h3);
    cudaGetSymbolAddress((void**)&z, g_z);
    cudaGetSymbolAddress((void**)&quant, g_quant);
    cudaGetSymbolAddress((void**)&qh, g_qh);
    cudaGetSymbolAddress((void**)&ql, g_ql);
    cudaGetSymbolAddress((void**)&d1h, g_d1h);
    cudaGetSymbolAddress((void**)&d1l, g_d1l);
    cudaGetSymbolAddress((void**)&d2, g_d2);
    cudaGetSymbolAddress((void**)&znorm, g_znorm);
    cudaGetSymbolAddress((void**)&cnorm, g_cnorm);
    cudaGetSymbolAddress((void**)&idx, g_idx);
    cudaGetSymbolAddress((void**)&commit, g_commit);
    cudaGetSymbolAddress((void**)&apk, g_apk);
    cudaGetSymbolAddress((void**)&bpk, g_bpk);
    cudaGetSymbolAddress((void**)&bv8, g_bv8);
    cudaGetSymbolAddress((void**)&bi8, g_bi8);
    cudaGetSymbolAddress((void**)&wd1h, g_wd1h); cudaGetSymbolAddress((void**)&wd1l, g_wd1l);
    cudaGetSymbolAddress((void**)&wt2h, g_wt2h); cudaGetSymbolAddress((void**)&wt2l, g_wt2l);

    cudaFuncSetAttribute(conv_mma<0,3,1,1,true ,1>, cudaFuncAttributeMaxDynamicSharedMemorySize, CMMA_SMEM);
    cudaFuncSetAttribute(conv_mma<1,4,2,1,true ,0>, cudaFuncAttributeMaxDynamicSharedMemorySize, CMMA_SMEM);

    // weight prep (decoder splits + VQ codebook)
    wsplit<<<576, 256>>>(dec_w1, wd1h, wd1l, 128 * 1152);
    pack_wt2<<<1024, 256>>>(dect_w2, wt2h, wt2l);
    pack_c_bf16<<<KCB, 256>>>(codebook, bpk);
    rownorm_kernel<<<1024, 256>>>(codebook, cnorm, KCB);
    zero_commit_kernel<<<1, 1>>>(commit);

    // encoder — exact R1 FFMA path (bitwise-stable z)
    conv_gemm<4,2,1,true ,0,0><<<dim3(256,1,4),256>>>(x,  enc_w1, enc_b1, h1, nullptr, nullptr,
                                                      3,  128, 256,256, 128,128, 7);
    conv_gemm<4,2,1,true ,0,0><<<dim3( 64,1,4),256>>>(h1, enc_w2, enc_b2, h2, nullptr, nullptr,
                                                      128,128, 128,128,  64, 64, 6);
    conv_gemm<3,1,1,false,0,0><<<dim3( 64,1,4),256>>>(h2, enc_w3, enc_b3, h3, nullptr, nullptr,
                                                      128,128,  64, 64,  64, 64, 6);
    conv_gemm<1,1,0,false,0,1><<<dim3( 64,2,4),256>>>(h3, qconv_w, qconv_b, z, nullptr, nullptr,
                                                      128,256,  64, 64,  64, 64, 6);

    // quantize — exact R3 path
    pack_z_bf16<<<NQ, 256>>>(z, apk);
    rownorm_kernel<<<2048, 256>>>(z, znorm, NQ);
    vq_mma<<<dim3(128, 8), 256>>>(apk, bpk, znorm, cnorm, bv8, bi8);
    vq_combine8<<<64, 256>>>(bv8, bi8, idx);
    gather_commit<<<NQ, 256>>>(codebook, z, idx, quant, commit);

    // decoder — tensor-core bf16-split (safe: downstream of idx)
    conv_gemm<1,1,0,false,1,2><<<dim3(64,1,4),256>>>(quant, pqconv_w, pqconv_b, nullptr, qh, ql,
                                                     256, 128, 64,64, 64,64, 6);
    conv_mma<0,3,1,1,true ,1><<<dim3(32,1,4),256,CMMA_SMEM>>>(qh, ql, wd1h, wd1l, dec_b1,
                                                     nullptr, d1h, d1l, 128, 64, 64, 1152);
    conv_mma<1,4,2,1,true ,0><<<dim3(32,4,4),256,CMMA_SMEM>>>(d1h, d1l, wt2h, wt2l, dect_b2,
                                                     d2, nullptr, nullptr, 128, 64, 64, 512);
    convt_out3<<<dim3(256,4),256>>>(d2, dect_w3, dect_b3, out);

    pack_kernel<<<64, 256>>>(out, commit, idx);

    (void)in_sizes; (void)n_in; (void)out_size;
}

// round 6
// speedup vs baseline: 2.3008x; 1.0370x over previous
#include <cuda_runtime.h>
#include <cuda_bf16.h>
#include <cstdint>

// ---------------- problem constants ----------------
#define BATCH 4
#define NQ    16384
#define EDIM  256
#define KCB   8192
#define KP    768            // packed K' = 3 * 256 for VQ GEMM

// ---------------- scratch (static device memory; no allocation) ----------------
__device__ float g_h1[4 * 128 * 128 * 128];
__device__ float g_h2[4 * 128 * 64 * 64];
__device__ float g_h3[4 * 128 * 64 * 64];
__device__ float g_z[NQ * EDIM];
__device__ float g_quant[NQ * EDIM];
__device__ __nv_bfloat16 g_qh[4 * 128 * 64 * 64];
__device__ __nv_bfloat16 g_ql[4 * 128 * 64 * 64];
__device__ __nv_bfloat16 g_d1h[4 * 128 * 64 * 64];
__device__ __nv_bfloat16 g_d1l[4 * 128 * 64 * 64];
__device__ float g_d2[4 * 128 * 128 * 128];
__device__ float g_znorm[NQ];
__device__ float g_cnorm[KCB];
__device__ int   g_idx[NQ];
__device__ float g_commit;
// VQ packed split buffers
__device__ __nv_bfloat16 g_apk[(size_t)NQ * KP];
__device__ __nv_bfloat16 g_bpk[(size_t)KCB * KP];
__device__ float g_bv8[8 * NQ];
__device__ int   g_bi8[8 * NQ];
// pre-split decoder weights
__device__ __nv_bfloat16 g_wd1h[128 * 1152], g_wd1l[128 * 1152];
__device__ __nv_bfloat16 g_wt2h[4 * 128 * 512], g_wt2l[4 * 128 * 512];

__device__ __forceinline__ uint32_t s2u(const void* p)
{
    uint32_t a;
    asm("{ .reg .u64 t; cvta.to.shared.u64 t, %1; cvt.u32.u64 %0, t; }" : "=r"(a) : "l"(p));
    return a;
}

#define CP16(dst, src) \
    asm volatile("cp.async.cg.shared.global [%0], [%1], 16;" :: "r"(dst), "l"(src) : "memory")
#define CP_COMMIT() asm volatile("cp.async.commit_group;" ::: "memory")
#define CP_WAIT1()  asm volatile("cp.async.wait_group 1;" ::: "memory")
#define CP_WAIT0()  asm volatile("cp.async.wait_group 0;" ::: "memory")

__device__ __forceinline__ void mma_bf16(float* c, const uint32_t* a, const uint32_t* b)
{
    asm volatile(
        "mma.sync.aligned.m16n8k16.row.col.f32.bf16.bf16.f32 "
        "{%0,%1,%2,%3}, {%4,%5,%6,%7}, {%8,%9}, {%0,%1,%2,%3};"
        : "+f"(c[0]), "+f"(c[1]), "+f"(c[2]), "+f"(c[3])
        : "r"(a[0]), "r"(a[1]), "r"(a[2]), "r"(a[3]), "r"(b[0]), "r"(b[1]));
}

__device__ __forceinline__ void ffma2(uint64_t& acc, uint64_t wp, uint64_t xx)
{
    asm("fma.rn.f32x2 %0, %1, %2, %0;" : "+l"(acc) : "l"(wp), "l"(xx));
}

// =====================================================================
// FFMA2 implicit-GEMM conv — per-output accumulation chain is ascending-k
// single fp32 fma per lane => BITWISE IDENTICAL to the R1/R5 FFMA kernel.
// OUTL: 0 = NCHW f32, 1 = [n][Cout] f32, 2 = bf16 split planes NCHW.
// =====================================================================
template<int KK, int S, int P, bool RELU, int INL, int OUTL>
__global__ __launch_bounds__(256)
void conv_gemm(const float* __restrict__ in, const float* __restrict__ w,
               const float* __restrict__ bias, float* __restrict__ out,
               __nv_bfloat16* __restrict__ outh, __nv_bfloat16* __restrict__ outl,
               int Cin, int Cout, int Hin, int Win, int Hout, int Wout,
               int woutShift)
{
    const int R = Cin * KK * KK;
    const int b = blockIdx.z;
    const int oc0 = blockIdx.y * 128;
    const int pxbase = blockIdx.x * 64;

    __shared__ __align__(16) float ws[16][128];
    __shared__ __align__(16) float xs[16][68];

    const int tid = threadIdx.x;
    const int tx = tid & 15;
    const int ty = tid >> 4;

    const uint32_t wsb = s2u(ws) + ty * 32;   // &ws[0][ty*8]

    // acc2[p][i]: oc pair (ty*8+2p, ty*8+2p+1) x px (tx*4+i); lo word = even oc
    uint64_t acc2[4][4];
#pragma unroll
    for (int p = 0; p < 4; p++)
#pragma unroll
        for (int i = 0; i < 4; i++) acc2[p][i] = 0ull;

    for (int r0 = 0; r0 < R; r0 += 16) {
        __syncthreads();
        {
            int row = tid >> 1;
            int half = tid & 1;
            int oc = oc0 + row;
#pragma unroll
            for (int i = 0; i < 8; i++) {
                int r = r0 + half * 8 + i;
                ws[half * 8 + i][row] = (r < R) ? w[oc * R + r] : 0.f;
            }
        }
#pragma unroll
        for (int i2 = 0; i2 < 4; i2++) {
            int li = tid + i2 * 256;
            int r, p;
            if (INL == 1) { r = li & 15; p = li >> 4; }
            else          { r = li >> 6; p = li & 63; }
            int rr = r0 + r;
            float v = 0.f;
            if (rr < R) {
                if (INL == 1) {
                    int n = b * (Hout * Wout) + pxbase + p;
                    v = in[(size_t)n * Cin + rr];
                } else {
                    int ic = rr / (KK * KK);
                    int kr = rr - ic * KK * KK;
                    int kh = kr / KK, kw = kr - kh * KK;
                    int px = pxbase + p;
                    int oh = px >> woutShift;
                    int ow = px & (Wout - 1);
                    int ih = oh * S + kh - P;
                    int iw = ow * S + kw - P;
                    if ((unsigned)ih < (unsigned)Hin && (unsigned)iw < (unsigned)Win)
                        v = in[((size_t)(b * Cin + ic) * Hin + ih) * Win + iw];
                }
            }
            xs[r][p] = v;
        }
        __syncthreads();
#pragma unroll
        for (int k = 0; k < 16; k++) {
            float4 xv = *reinterpret_cast<const float4*>(&xs[k][tx * 4]);
            uint64_t wp0, wp1, wp2, wp3;
            asm("ld.shared.v2.u64 {%0,%1}, [%2];"
                : "=l"(wp0), "=l"(wp1) : "r"(wsb + (uint32_t)(k * 512)));
            asm("ld.shared.v2.u64 {%0,%1}, [%2];"
                : "=l"(wp2), "=l"(wp3) : "r"(wsb + (uint32_t)(k * 512 + 16)));
            uint64_t xx0, xx1, xx2, xx3;
            asm("mov.b64 %0, {%1,%1};" : "=l"(xx0) : "f"(xv.x));
            asm("mov.b64 %0, {%1,%1};" : "=l"(xx1) : "f"(xv.y));
            asm("mov.b64 %0, {%1,%1};" : "=l"(xx2) : "f"(xv.z));
            asm("mov.b64 %0, {%1,%1};" : "=l"(xx3) : "f"(xv.w));
            ffma2(acc2[0][0], wp0, xx0); ffma2(acc2[0][1], wp0, xx1);
            ffma2(acc2[0][2], wp0, xx2); ffma2(acc2[0][3], wp0, xx3);
            ffma2(acc2[1][0], wp1, xx0); ffma2(acc2[1][1], wp1, xx1);
            ffma2(acc2[1][2], wp1, xx2); ffma2(acc2[1][3], wp1, xx3);
            ffma2(acc2[2][0], wp2, xx0); ffma2(acc2[2][1], wp2, xx1);
            ffma2(acc2[2][2], wp2, xx2); ffma2(acc2[2][3], wp2, xx3);
            ffma2(acc2[3][0], wp3, xx0); ffma2(acc2[3][1], wp3, xx1);
            ffma2(acc2[3][2], wp3, xx2); ffma2(acc2[3][3], wp3, xx3);
        }
    }

#pragma unroll
    for (int p = 0; p < 4; p++)
#pragma unroll
        for (int half = 0; half < 2; half++) {
            int j = 2 * p + half;
            int oc = oc0 + ty * 8 + j;
            float bv = bias[oc];
#pragma unroll
            for (int i = 0; i < 4; i++) {
                uint32_t bits = half ? (uint32_t)(acc2[p][i] >> 32)
                                     : (uint32_t)(acc2[p][i] & 0xffffffffull);
                float v = __uint_as_float(bits) + bv;
                if (RELU) v = fmaxf(v, 0.f);
                if (OUTL == 1) {
                    size_t n = (size_t)(b * (Hout * Wout) + pxbase + tx * 4 + i);
                    out[n * Cout + oc] = v;
                } else {
                    size_t addr = (size_t)(b * Cout + oc) * (Hout * Wout) + pxbase + tx * 4 + i;
                    if (OUTL == 0) {
                        out[addr] = v;
                    } else {
                        __nv_bfloat16 h = __float2bfloat16(v);
                        outh[addr] = h;
                        outl[addr] = __float2bfloat16(v - __bfloat162float(h));
                    }
                }
            }
        }
}

// =====================================================================
// Tensor-core implicit-GEMM conv, bf16 3-term split — DECODER ONLY.
// (unchanged from R5 — passing)
// =====================================================================
#define CLDA 40
#define ABUF 5120

template<int MODE, int KK, int S, int P, bool RELU, int OUTMODE>
__global__ __launch_bounds__(256)
void conv_mma(const __nv_bfloat16* __restrict__ xh, const __nv_bfloat16* __restrict__ xl,
              const __nv_bfloat16* __restrict__ wh_g, const __nv_bfloat16* __restrict__ wl_g,
              const float* __restrict__ bias,
              float* __restrict__ outf, __nv_bfloat16* __restrict__ outh,
              __nv_bfloat16* __restrict__ outl,
              int Cin, int Hin, int Win, int R)
{
    extern __shared__ __align__(16) char sm[];
    __nv_bfloat16* sA_h = (__nv_bfloat16*)(sm);
    __nv_bfloat16* sA_l = (__nv_bfloat16*)(sm + 20480);
    __nv_bfloat16* sB_h = (__nv_bfloat16*)(sm + 40960);
    __nv_bfloat16* sB_l = (__nv_bfloat16*)(sm + 61440);
    float* biasS = (float*)(sm + 81920);

    const int tid = threadIdx.x;
    const int lane = tid & 31, wid = tid >> 5;
    const int wm = wid & 3, wn = wid >> 2;
    const int lr = lane >> 2, lc = lane & 3;
    const int b = blockIdx.z;

    int pxbase = 0, j0 = 0, ohp = 0, owp = 0;
    const __nv_bfloat16* wh = wh_g;
    const __nv_bfloat16* wl = wl_g;
    if (MODE == 1) {
        j0 = blockIdx.x * 2;
        int cls = blockIdx.y;
        ohp = cls >> 1; owp = cls & 1;
        wh = wh_g + cls * (128 * 512);
        wl = wl_g + cls * (128 * 512);
    } else {
        pxbase = blockIdx.x * 128;
    }

    if (tid < 128) biasS[tid] = bias[tid];

    const int NC = R >> 5;

    const int boc = tid >> 1;
    const uint32_t sbBh = s2u(sB_h), sbBl = s2u(sB_l);
    const uint32_t bOff = (uint32_t)(boc * 80 + (tid & 1) * 32);
    const size_t bSrc = (size_t)boc * R + (tid & 1) * 16;

    const int kloc = tid & 31, pblk = tid >> 5;

    float acc[2][8][4];
#pragma unroll
    for (int mf = 0; mf < 2; mf++)
#pragma unroll
        for (int nf = 0; nf < 8; nf++)
#pragma unroll
            for (int e = 0; e < 4; e++) acc[mf][nf][e] = 0.f;

    __nv_bfloat16 pvh[16], pvl[16];

    auto cpB = [&](int r0, int bf) {
        uint32_t d = (uint32_t)bf * 10240;
        const __nv_bfloat16* sh = wh + bSrc + r0;
        const __nv_bfloat16* sl = wl + bSrc + r0;
        CP16(sbBh + d + bOff, sh);  CP16(sbBh + d + bOff + 16, sh + 8);
        CP16(sbBl + d + bOff, sl);  CP16(sbBl + d + bOff + 16, sl + 8);
    };

    auto ldgA = [&](int r0) {
        int r = r0 + kloc;
        if (MODE == 0) {
            int ic = r / (KK * KK);
            int rem = r - ic * KK * KK;
            int kh = rem / KK, kw = rem - kh * KK;
            int px = pxbase + pblk * 16;
            int oh = px >> 6, ow0 = px & 63;
            int ih = oh * S + kh - P;
            const size_t rowb = ((size_t)(b * Cin + ic) * Hin + ih) * Win;
            bool okh = (unsigned)ih < (unsigned)Hin;
#pragma unroll
            for (int i = 0; i < 16; i++) {
                int iw = (ow0 + i) * S + kw - P;
                bool ok = okh && (unsigned)iw < (unsigned)Win;
                pvh[i] = ok ? xh[rowb + iw] : __float2bfloat16(0.f);
                pvl[i] = ok ? xl[rowb + iw] : __float2bfloat16(0.f);
            }
        } else {
            int ic = r >> 2, th = (r >> 1) & 1, tw = r & 1;
            int j = j0 + (pblk >> 2);
            int i0 = (pblk & 3) * 16;
            int ih = j + (1 - ohp) - th;
            int iwb = i0 + (1 - owp) - tw;
            const size_t rowb = ((size_t)(b * Cin + ic) * 64 + ih) * 64;
            bool okh = (unsigned)ih < 64u;
#pragma unroll
            for (int i = 0; i < 16; i++) {
                int iw = iwb + i;
                bool ok = okh && (unsigned)iw < 64u;
                pvh[i] = ok ? xh[rowb + iw] : __float2bfloat16(0.f);
                pvl[i] = ok ? xl[rowb + iw] : __float2bfloat16(0.f);
            }
        }
    };

    auto stsA = [&](int bf) {
        int base = bf * ABUF + kloc;
#pragma unroll
        for (int i = 0; i < 16; i++) {
            int p = pblk * 16 + i;
            sA_h[base + p * CLDA] = pvh[i];
            sA_l[base + p * CLDA] = pvl[i];
        }
    };

    auto domma = [&](int bf) {
        const int off = bf * ABUF;
#pragma unroll
        for (int ks = 0; ks < 2; ks++) {
            const int k0 = ks * 16 + lc * 2;
            uint32_t ah[2][4], al[2][4];
#pragma unroll
            for (int mf = 0; mf < 2; mf++) {
                int r1 = wm * 32 + mf * 16 + lr;
                ah[mf][0] = *(const uint32_t*)&sA_h[off + r1 * CLDA + k0];
                ah[mf][1] = *(const uint32_t*)&sA_h[off + (r1 + 8) * CLDA + k0];
                ah[mf][2] = *(const uint32_t*)&sA_h[off + r1 * CLDA + k0 + 8];
                ah[mf][3] = *(const uint32_t*)&sA_h[off + (r1 + 8) * CLDA + k0 + 8];
                al[mf][0] = *(const uint32_t*)&sA_l[off + r1 * CLDA + k0];
                al[mf][1] = *(const uint32_t*)&sA_l[off + (r1 + 8) * CLDA + k0];
                al[mf][2] = *(const uint32_t*)&sA_l[off + r1 * CLDA + k0 + 8];
                al[mf][3] = *(const uint32_t*)&sA_l[off + (r1 + 8) * CLDA + k0 + 8];
            }
#pragma unroll
            for (int nf = 0; nf < 8; nf++) {
                int cr = wn * 64 + nf * 8 + lr;
                uint32_t bh[2], bl[2];
                bh[0] = *(const uint32_t*)&sB_h[off + cr * CLDA + k0];
                bh[1] = *(const uint32_t*)&sB_h[off + cr * CLDA + k0 + 8];
                bl[0] = *(const uint32_t*)&sB_l[off + cr * CLDA + k0];
                bl[1] = *(const uint32_t*)&sB_l[off + cr * CLDA + k0 + 8];
#pragma unroll
                for (int mf = 0; mf < 2; mf++) {
                    mma_bf16(acc[mf][nf], ah[mf], bh);
                    mma_bf16(acc[mf][nf], al[mf], bh);
                    mma_bf16(acc[mf][nf], ah[mf], bl);
                }
            }
        }
    };

    cpB(0, 0); CP_COMMIT();
    ldgA(0); stsA(0);
    for (int kc = 0; kc < NC; kc++) {
        const int bf = kc & 1;
        const bool nxt = (kc + 1 < NC);
        if (nxt) {
            cpB((kc + 1) * 32, bf ^ 1); CP_COMMIT();
            ldgA((kc + 1) * 32);
            CP_WAIT1();
        } else {
            CP_WAIT0();
        }
        __syncthreads();
        domma(bf);
        if (nxt) stsA(bf ^ 1);
        __syncthreads();
    }

#pragma unroll
    for (int mf = 0; mf < 2; mf++)
#pragma unroll
        for (int nf = 0; nf < 8; nf++)
#pragma unroll
            for (int e = 0; e < 4; e++) {
                int row = wm * 32 + mf * 16 + lr + (e >> 1) * 8;
                int oc = wn * 64 + nf * 8 + lc * 2 + (e & 1);
                float v = acc[mf][nf][e] + biasS[oc];
                if (RELU) v = fmaxf(v, 0.f);
                size_t addr;
                if (MODE == 0) {
                    int px = pxbase + row;
                    addr = ((size_t)(b * 128 + oc) * 64 + (px >> 6)) * 64 + (px & 63);
                } else {
                    int oh = (1 - ohp) + 2 * (j0 + (row >> 6));
                    int ow = (1 - owp) + 2 * (row & 63);
                    addr = ((size_t)(b * 128 + oc) * 128 + oh) * 128 + ow;
                }
                if (OUTMODE == 0) {
                    outf[addr] = v;
                } else {
                    __nv_bfloat16 h = __float2bfloat16(v);
                    outh[addr] = h;
                    outl[addr] = __float2bfloat16(v - __bfloat162float(h));
                }
            }
}

// =====================================================================
// weight split kernels (decoder only)
// =====================================================================
__global__ void wsplit(const float* __restrict__ w, __nv_bfloat16* __restrict__ wh,
                       __nv_bfloat16* __restrict__ wl, int n)
{
    int i = blockIdx.x * 256 + threadIdx.x;
    if (i >= n) return;
    float x = w[i];
    __nv_bfloat16 h = __float2bfloat16(x);
    wh[i] = h;
    wl[i] = __float2bfloat16(x - __bfloat162float(h));
}

__global__ void pack_wt2(const float* __restrict__ w, __nv_bfloat16* __restrict__ wh,
                         __nv_bfloat16* __restrict__ wl)
{
    int i = blockIdx.x * 256 + threadIdx.x;      // over 4*128*512
    int cls = i >> 16;
    int oc = (i >> 9) & 127;
    int r = i & 511;
    int ohp = cls >> 1, owp = cls & 1;
    int ic = r >> 2, th = (r >> 1) & 1, tw = r & 1;
    float x = w[((ic * 128 + oc) * 4 + ohp + 2 * th) * 4 + owp + 2 * tw];
    __nv_bfloat16 h = __float2bfloat16(x);
    wh[i] = h;
    wl[i] = __float2bfloat16(x - __bfloat162float(h));
}

// =====================================================================
// row squared-norm (exact R1 arithmetic)
// =====================================================================
__global__ void rownorm_kernel(const float* __restrict__ v, float* __restrict__ outn, int rows)
{
    int warp = threadIdx.x >> 5, lane = threadIdx.x & 31;
    int n = blockIdx.x * 8 + warp;
    if (n >= rows) return;
    const float* p = v + (size_t)n * 256;
    float s = 0.f;
#pragma unroll
    for (int k = 0; k < 8; k++) { float x = p[lane + 32 * k]; s = fmaf(x, x, s); }
#pragma unroll
    for (int off = 16; off; off >>= 1) s += __shfl_down_sync(0xffffffffu, s, off);
    if (lane == 0) outn[n] = s;
}

__global__ void zero_commit_kernel(float* c) { *c = 0.f; }

// =====================================================================
// VQ pack kernels (exact R3)
// =====================================================================
__global__ void pack_z_bf16(const float* __restrict__ z, __nv_bfloat16* __restrict__ A)
{
    int i = blockIdx.x * 256 + threadIdx.x;
    int q = i >> 8, k = i & 255;
    float x = z[i];
    __nv_bfloat16 h = __float2bfloat16(x);
    __nv_bfloat16 l = __float2bfloat16(x - __bfloat162float(h));
    size_t base = (size_t)q * KP;
    A[base + k] = h;
    A[base + 256 + k] = l;
    A[base + 512 + k] = h;
}

__global__ void pack_c_bf16(const float* __restrict__ c, __nv_bfloat16* __restrict__ B)
{
    int i = blockIdx.x * 256 + threadIdx.x;
    int q = i >> 8, k = i & 255;
    float x = c[i];
    __nv_bfloat16 h = __float2bfloat16(x);
    __nv_bfloat16 l = __float2bfloat16(x - __bfloat162float(h));
    size_t base = (size_t)q * KP;
    B[base + k] = h;
    B[base + 256 + k] = h;
    B[base + 512 + k] = l;
}

// =====================================================================
// VQ GEMM + fused argmin (exact R3 — passing)
// =====================================================================
#define LDA 40
#define BUFB (128 * LDA * 2)

__global__ __launch_bounds__(256)
void vq_mma(const __nv_bfloat16* __restrict__ Apk, const __nv_bfloat16* __restrict__ Bpk,
            const float* __restrict__ znorm, const float* __restrict__ cnorm,
            float* __restrict__ bv8, int* __restrict__ bi8)
{
    __shared__ __align__(16) __nv_bfloat16 sA[2][128 * LDA];
    __shared__ __align__(16) __nv_bfloat16 sB[2][128 * LDA];
    __shared__ float znS[128], cnS[128];
    __shared__ float redV[2][128];
    __shared__ int   redI[2][128];

    const int tid = threadIdx.x;
    const int lane = tid & 31, wid = tid >> 5;
    const int wm = wid & 3, wn = wid >> 2;
    const int lr = lane >> 2, lc = lane & 3;
    const int qbase = blockIdx.x * 128;
    const int gbase = blockIdx.y * 1024;

    if (tid < 128) znS[tid] = znorm[qbase + tid];
    __syncthreads();
    float znr[4];
#pragma unroll
    for (int s = 0; s < 4; s++)
        znr[s] = znS[wm * 32 + (s >> 1) * 16 + lr + (s & 1) * 8];

    float bestv[4] = {3.4e38f, 3.4e38f, 3.4e38f, 3.4e38f};
    int   besti[4] = {0, 0, 0, 0};

    float acc[2][8][4];
#pragma unroll
    for (int mf = 0; mf < 2; mf++)
#pragma unroll
        for (int nf = 0; nf < 8; nf++)
#pragma unroll
            for (int e = 0; e < 4; e++) acc[mf][nf][e] = 0.f;

    const int srow = tid >> 1;
    const __nv_bfloat16* asrc = Apk + (size_t)(qbase + srow) * KP + (tid & 1) * 16;
    const uint32_t saA = s2u(sA) + srow * (LDA * 2) + (tid & 1) * 32;
    const uint32_t saB = s2u(sB) + srow * (LDA * 2) + (tid & 1) * 32;

    for (int nt = 0; nt < 8; nt++) {
        const __nv_bfloat16* bsrc =
            Bpk + (size_t)(gbase + nt * 128 + srow) * KP + (tid & 1) * 16;
        if (tid < 128) cnS[tid] = cnorm[gbase + nt * 128 + tid];

        CP16(saA, asrc);      CP16(saA + 16, asrc + 8);
        CP16(saB, bsrc);      CP16(saB + 16, bsrc + 8);
        CP_COMMIT();

        for (int kc = 0; kc < 24; kc++) {
            if (kc + 1 < 24) {
                const uint32_t nb = (uint32_t)((kc + 1) & 1) * BUFB;
                const __nv_bfloat16* a2 = asrc + (kc + 1) * 32;
                const __nv_bfloat16* b2 = bsrc + (kc + 1) * 32;
                CP16(saA + nb, a2);      CP16(saA + nb + 16, a2 + 8);
                CP16(saB + nb, b2);      CP16(saB + nb + 16, b2 + 8);
                CP_COMMIT();
                CP_WAIT1();
            } else {
                CP_WAIT0();
            }
            __syncthreads();

            const int buf = kc & 1;
#pragma unroll
            for (int ks = 0; ks < 2; ks++) {
                const int k0 = ks * 16 + lc * 2;
                uint32_t a[2][4], b[8][2];
#pragma unroll
                for (int mf = 0; mf < 2; mf++) {
                    int r = wm * 32 + mf * 16 + lr;
                    a[mf][0] = *(const uint32_t*)&sA[buf][r * LDA + k0];
                    a[mf][1] = *(const uint32_t*)&sA[buf][(r + 8) * LDA + k0];
                    a[mf][2] = *(const uint32_t*)&sA[buf][r * LDA + k0 + 8];
                    a[mf][3] = *(const uint32_t*)&sA[buf][(r + 8) * LDA + k0 + 8];
                }
#pragma unroll
                for (int nf = 0; nf < 8; nf++) {
                    int cr = wn * 64 + nf * 8 + lr;
                    b[nf][0] = *(const uint32_t*)&sB[buf][cr * LDA + k0];
                    b[nf][1] = *(const uint32_t*)&sB[buf][cr * LDA + k0 + 8];
                }
#pragma unroll
                for (int mf = 0; mf < 2; mf++)
#pragma unroll
                    for (int nf = 0; nf < 8; nf++)
                        mma_bf16(acc[mf][nf], a[mf], b[nf]);
            }
            __syncthreads();
        }

#pragma unroll
        for (int mf = 0; mf < 2; mf++)
#pragma unroll
            for (int nf = 0; nf < 8; nf++)
#pragma unroll
                for (int e = 0; e < 4; e++) {
                    int h = e >> 1;
                    int col = wn * 64 + nf * 8 + lc * 2 + (e & 1);
                    int slot = mf * 2 + h;
                    float t = znr[slot] + cnS[col];
                    float s = fmaf(-2.f, acc[mf][nf][e], t);
                    int code = gbase + nt * 128 + col;
                    if (s < bestv[slot]) { bestv[slot] = s; besti[slot] = code; }
                    acc[mf][nf][e] = 0.f;
                }
        __syncthreads();
    }

#pragma unroll
    for (int s = 0; s < 4; s++) {
        float v = bestv[s]; int ix = besti[s];
#pragma unroll
        for (int off = 1; off <= 2; off <<= 1) {
            float ov = __shfl_xor_sync(0xffffffffu, v, off);
            int   oi = __shfl_xor_sync(0xffffffffu, ix, off);
            if (ov < v || (ov == v && oi < ix)) { v = ov; ix = oi; }
        }
        if (lc == 0) {
            int row = wm * 32 + (s >> 1) * 16 + lr + (s & 1) * 8;
            redV[wn][row] = v; redI[wn][row] = ix;
        }
    }
    __syncthreads();
    if (tid < 128) {
        float v = redV[0][tid]; int ix = redI[0][tid];
        float v1 = redV[1][tid]; int i1 = redI[1][tid];
        if (v1 < v || (v1 == v && i1 < ix)) { v = v1; ix = i1; }
        bv8[blockIdx.y * NQ + qbase + tid] = v;
        bi8[blockIdx.y * NQ + qbase + tid] = ix;
    }
}

__global__ void vq_combine8(const float* __restrict__ bv8, const int* __restrict__ bi8,
                            int* __restrict__ idx)
{
    int q = blockIdx.x * 256 + threadIdx.x;
    if (q >= NQ) return;
    float v = bv8[q]; int ix = bi8[q];
#pragma unroll
    for (int g = 1; g < 8; g++) {
        float v2 = bv8[g * NQ + q];
        int   i2 = bi8[g * NQ + q];
        if (v2 < v || (v2 == v && i2 < ix)) { v = v2; ix = i2; }
    }
    idx[q] = ix;
}

// =====================================================================
// gather quant = codebook[idx], commit loss
// =====================================================================
__global__ __launch_bounds__(256)
void gather_commit(const float* __restrict__ cb, const float* __restrict__ z,
                   const int* __restrict__ idx, float* __restrict__ quant,
                   float* __restrict__ commit)
{
    int n = blockIdx.x;
    int t = threadIdx.x;
    int id = idx[n];
    float q = cb[(size_t)id * 256 + t];
    float zv = z[(size_t)n * 256 + t];
    quant[(size_t)n * 256 + t] = q;
    float d = q - zv; d *= d;
#pragma unroll
    for (int off = 16; off; off >>= 1) d += __shfl_down_sync(0xffffffffu, d, off);
    __shared__ float wsum[8];
    int warp = t >> 5, lane = t & 31;
    if (lane == 0) wsum[warp] = d;
    __syncthreads();
    if (t == 0) {
        float s = 0.f;
#pragma unroll
        for (int w = 0; w < 8; w++) s += wsum[w];
        atomicAdd(commit, s);
    }
}

// =====================================================================
// Final transposed conv (128 -> 3 channels) straight into d_out
// =====================================================================
__global__ __launch_bounds__(256)
void convt_out3(const float* __restrict__ in, const float* __restrict__ w,
                const float* __restrict__ bias, float* __restrict__ out)
{
    __shared__ float ws[128 * 3 * 16];
    for (int i = threadIdx.x; i < 6144; i += 256) ws[i] = w[i];
    __syncthreads();

    int b = blockIdx.y, oh = blockIdx.x, ow = threadIdx.x;
    int ih0 = (oh + 1) >> 1, kh0 = (oh + 1) & 1;
    int iw0 = (ow + 1) >> 1, kw0 = (ow + 1) & 1;

    float acc0 = 0.f, acc1 = 0.f, acc2 = 0.f;
    for (int ic = 0; ic < 128; ic++) {
        const float* inp = in + ((size_t)(b * 128 + ic)) * 128 * 128;
        const float* wp = ws + ic * 48;
#pragma unroll
        for (int th = 0; th < 2; th++) {
            int ih = ih0 - th;
            if ((unsigned)ih < 128u) {
                int kh = kh0 + 2 * th;
#pragma unroll
                for (int tw = 0; tw < 2; tw++) {
                    int iw = iw0 - tw;
                    if ((unsigned)iw < 128u) {
                        int kw = kw0 + 2 * tw;
                        float v = inp[ih * 128 + iw];
                        int wk = kh * 4 + kw;
                        acc0 = fmaf(v, wp[wk], acc0);
                        acc1 = fmaf(v, wp[16 + wk], acc1);
                        acc2 = fmaf(v, wp[32 + wk], acc2);
                    }
                }
            }
        }
    }
    size_t ob = ((size_t)(b * 3) * 256 + oh) * 256 + ow;
    out[ob]          = acc0 + bias[0];
    out[ob + 65536]  = acc1 + bias[1];
    out[ob + 131072] = acc2 + bias[2];
}

__global__ void pack_kernel(float* __restrict__ out, const float* __restrict__ commit,
                            const int* __restrict__ idx)
{
    int i = blockIdx.x * 256 + threadIdx.x;
    if (i == 0) out[786432] = (*commit) * (1.f / 4194304.f);
    if (i < NQ) out[786433 + i] = (float)idx[i];
}

// =====================================================================
// host launcher
// =====================================================================
#define CMMA_SMEM 82432

extern "C" void kernel_launch(void* const* d_in, const int* in_sizes, int n_in,
                              void* d_out, int out_size)
{
    const float* x        = (const float*)d_in[0];
    const float* enc_w1   = (const float*)d_in[1];
    const float* enc_b1   = (const float*)d_in[2];
    const float* enc_w2   = (const float*)d_in[3];
    const float* enc_b2   = (const float*)d_in[4];
    const float* enc_w3   = (const float*)d_in[5];
    const float* enc_b3   = (const float*)d_in[6];
    const float* qconv_w  = (const float*)d_in[7];
    const float* qconv_b  = (const float*)d_in[8];
    const float* codebook = (const float*)d_in[9];
    const float* pqconv_w = (const float*)d_in[10];
    const float* pqconv_b = (const float*)d_in[11];
    const float* dec_w1   = (const float*)d_in[12];
    const float* dec_b1   = (const float*)d_in[13];
    const float* dect_w2  = (const float*)d_in[14];
    const float* dect_b2  = (const float*)d_in[15];
    const float* dect_w3  = (const float*)d_in[16];
    const float* dect_b3  = (const float*)d_in[17];
    float* out = (float*)d_out;

    float *h1, *h2, *h3, *z, *quant, *d2, *znorm, *cnorm, *commit, *bv8;
    __nv_bfloat16 *qh, *ql, *d1h, *d1l, *apk, *bpk;
    __nv_bfloat16 *wd1h, *wd1l, *wt2h, *wt2l;
    int *idx, *bi8;
    cudaGetSymbolAddress((void**)&h1, g_h1);
    cudaGetSymbolAddress((void**)&h2, g_h2);
    cudaGetSymbolAddress((void**)&h3, g_h3);
    cudaGetSymbolAddress((void**)&z, g_z);
    cudaGetSymbolAddress((void**)&quant, g_quant);
    cudaGetSymbolAddress((void**)&qh, g_qh);
    cudaGetSymbolAddress((void**)&ql, g_ql);
    cudaGetSymbolAddress((void**)&d1h, g_d1h);
    cudaGetSymbolAddress((void**)&d1l, g_d1l);
    cudaGetSymbolAddress((void**)&d2, g_d2);
    cudaGetSymbolAddress((void**)&znorm, g_znorm);
    cudaGetSymbolAddress((void**)&cnorm, g_cnorm);
    cudaGetSymbolAddress((void**)&idx, g_idx);
    cudaGetSymbolAddress((void**)&commit, g_commit);
    cudaGetSymbolAddress((void**)&apk, g_apk);
    cudaGetSymbolAddress((void**)&bpk, g_bpk);
    cudaGetSymbolAddress((void**)&bv8, g_bv8);
    cudaGetSymbolAddress((void**)&bi8, g_bi8);
    cudaGetSymbolAddress((void**)&wd1h, g_wd1h); cudaGetSymbolAddress((void**)&wd1l, g_wd1l);
    cudaGetSymbolAddress((void**)&wt2h, g_wt2h); cudaGetSymbolAddress((void**)&wt2l, g_wt2l);

    cudaFuncSetAttribute(conv_mma<0,3,1,1,true ,1>, cudaFuncAttributeMaxDynamicSharedMemorySize, CMMA_SMEM);
    cudaFuncSetAttribute(conv_mma<1,4,2,1,true ,0>, cudaFuncAttributeMaxDynamicSharedMemorySize, CMMA_SMEM);

    // weight prep (decoder splits + VQ codebook)
    wsplit<<<576, 256>>>(dec_w1, wd1h, wd1l, 128 * 1152);
    pack_wt2<<<1024, 256>>>(dect_w2, wt2h, wt2l);
    pack_c_bf16<<<KCB, 256>>>(codebook, bpk);
    rownorm_kernel<<<1024, 256>>>(codebook, cnorm, KCB);
    zero_commit_kernel<<<1, 1>>>(commit);

    // encoder — FFMA2, bitwise-identical accumulation chains
    conv_gemm<4,2,1,true ,0,0><<<dim3(256,1,4),256>>>(x,  enc_w1, enc_b1, h1, nullptr, nullptr,
                                                      3,  128, 256,256, 128,128, 7);
    conv_gemm<4,2,1,true ,0,0><<<dim3( 64,1,4),256>>>(h1, enc_w2, enc_b2, h2, nullptr, nullptr,
                                                      128,128, 128,128,  64, 64, 6);
    conv_gemm<3,1,1,false,0,0><<<dim3( 64,1,4),256>>>(h2, enc_w3, enc_b3, h3, nullptr, nullptr,
                                                      128,128,  64, 64,  64, 64, 6);
    conv_gemm<1,1,0,false,0,1><<<dim3( 64,2,4),256>>>(h3, qconv_w, qconv_b, z, nullptr, nullptr,
                                                      128,256,  64, 64,  64, 64, 6);

    // quantize — exact R3 path
    pack_z_bf16<<<NQ, 256>>>(z, apk);
    rownorm_kernel<<<2048, 256>>>(z, znorm, NQ);
    vq_mma<<<dim3(128, 8), 256>>>(apk, bpk, znorm, cnorm, bv8, bi8);
    vq_combine8<<<64, 256>>>(bv8, bi8, idx);
    gather_commit<<<NQ, 256>>>(codebook, z, idx, quant, commit);

    // decoder — tensor-core bf16-split (safe: downstream of idx)
    conv_gemm<1,1,0,false,1,2><<<dim3(64,1,4),256>>>(quant, pqconv_w, pqconv_b, nullptr, qh, ql,
                                                     256, 128, 64,64, 64,64, 6);
    conv_mma<0,3,1,1,true ,1><<<dim3(32,1,4),256,CMMA_SMEM>>>(qh, ql, wd1h, wd1l, dec_b1,
                                                     nullptr, d1h, d1l, 128, 64, 64, 1152);
    conv_mma<1,4,2,1,true ,0><<<dim3(32,4,4),256,CMMA_SMEM>>>(d1h, d1l, wt2h, wt2l, dect_b2,
                                                     d2, nullptr, nullptr, 128, 64, 64, 512);
    convt_out3<<<dim3(256,4),256>>>(d2, dect_w3, dect_b3, out);

    pack_kernel<<<64, 256>>>(out, commit, idx);

    (void)in_sizes; (void)n_in; (void)out_size;
}